// round 13
// baseline (speedup 1.0000x reference)
#include <cuda_runtime.h>
#include <cstdint>

#define NN 50000
#define EE 800000
#define ET (EE + NN)
#define NB1 391                       // gemm1 blocks: ceil(50000/128)

// output layout: xo_logis [N,8] | xc_logis [N,8] | xco_logis [N,8] | elu(xo) [N,256] | elu(xc) [N,256]
#define O0 0
#define O1 (NN*8)
#define O2 (2*NN*8)
#define O3 (3*NN*8)
#define O4 (3*NN*8 + NN*256)

typedef unsigned long long ull;

__device__ __forceinline__ ull pk2(float lo, float hi) {
    ull r; asm("mov.b64 %0, {%1, %2};" : "=l"(r) : "f"(lo), "f"(hi)); return r;
}
__device__ __forceinline__ void upk2(ull v, float& lo, float& hi) {
    asm("mov.b64 {%0, %1}, %2;" : "=f"(lo), "=f"(hi) : "l"(v));
}
#define FMA2(d, a, b) asm("fma.rn.f32x2 %0, %1, %2, %0;" : "+l"(d) : "l"(a), "l"(b))

__device__ __forceinline__ void stcs4(float* p, float4 v) {
    asm volatile("st.global.cs.v4.f32 [%0], {%1,%2,%3,%4};" :: "l"(p),
                 "f"(v.x), "f"(v.y), "f"(v.z), "f"(v.w) : "memory");
}
__device__ __forceinline__ void stcs1(float* p, float v) {
    asm volatile("st.global.cs.f32 [%0], %1;" :: "l"(p), "f"(v) : "memory");
}
__device__ __forceinline__ int ldcs_i(const int* p) {
    int v; asm volatile("ld.global.cs.s32 %0, [%1];" : "=r"(v) : "l"(p)); return v;
}

// ------------------- static scratch (zero-initialized at module load) -------------------
__device__ int   g_deg[NN];          // ALWAYS zero at kernel_launch entry (scan re-zeroes)
__device__ int   g_rowptr[NN + 1];
__device__ int   g_wptr[NN];
__device__ int   g_srt[ET];

__device__ __align__(16) float  g_hfeat[(size_t)NN * 256];
__device__ __align__(16) float  g_h1[(size_t)NN * 256];
__device__ __align__(16) float2 g_att[NN];

__device__ __align__(16) float g_als[NN * 4], g_ald[NN * 4];
__device__ __align__(16) float g_gall[(size_t)NN * 48];
__device__ __align__(16) float g_alsP[NN * 8], g_aldP[NN * 8];

__device__ __forceinline__ float lrelu(float v) { return v > 0.f ? v : 0.2f * v; }
__device__ __forceinline__ float eluf(float v)  { return v > 0.f ? v : expm1f(v); }

// ------------------- CSR scan + scatter -------------------
__global__ void k_scan() {
    __shared__ int sums[1024];
    int tid = threadIdx.x;
    const int chunk = (NN + 1023) / 1024;
    int start = tid * chunk;
    int s = 0;
    for (int i = 0; i < chunk; i++) {
        int idx = start + i;
        if (idx < NN) s += g_deg[idx] + 1;   // +1 = self loop
    }
    sums[tid] = s;
    __syncthreads();
    for (int off = 1; off < 1024; off <<= 1) {
        int v = 0;
        if (tid >= off) v = sums[tid - off];
        __syncthreads();
        if (tid >= off) sums[tid] += v;
        __syncthreads();
    }
    int prefix = (tid == 0) ? 0 : sums[tid - 1];
    for (int i = 0; i < chunk; i++) {
        int idx = start + i;
        if (idx < NN) {
            g_rowptr[idx] = prefix;
            g_wptr[idx] = prefix;
            prefix += g_deg[idx] + 1;
            g_deg[idx] = 0;                  // restore invariant for next call
        }
    }
    if (tid == 0) g_rowptr[NN] = sums[1023];
}

__global__ void k_scatter(const int* __restrict__ ei) {
    int i = blockIdx.x * blockDim.x + threadIdx.x;
    if (i < EE / 2) {
        int2 s2 = ((const int2*)ei)[i];
        int2 d2 = ((const int2*)(ei + EE))[i];
        int p0 = atomicAdd(&g_wptr[d2.x], 1);
        g_srt[p0] = s2.x;
        int p1 = atomicAdd(&g_wptr[d2.y], 1);
        g_srt[p1] = s2.y;
    } else if (i < EE / 2 + NN) {
        int n = i - EE / 2;
        int pos = atomicAdd(&g_wptr[n], 1);
        g_srt[pos] = n;                      // self loop
    }
}

// ------------------- GEMM1: 128x256 tile, 512 thr, thread = 8 rows x (4+4 cols), fused hist -------------------
__global__ __launch_bounds__(512) void k_gemm1(
    const float* __restrict__ x, const float* __restrict__ Wf,
    const float* __restrict__ a_s, const float* __restrict__ a_d,
    const int* __restrict__ ei) {
    extern __shared__ float smem[];
    float (*xs)[128] = (float (*)[128])smem;                        // 128 x 128 = 64 KB
    float (*Bs)[8][256] = (float (*)[8][256])(smem + 128 * 128);    // [2][8][256] = 16 KB
    int tid = threadIdx.x;
    int n0 = blockIdx.x * 128;
    int ty = tid >> 5, tx = tid & 31;       // ty 0..15 -> 8-row group

    // fused edge histogram (independent of GEMM data flow)
    for (int i = blockIdx.x * 512 + tid; i < EE / 2; i += NB1 * 512) {
        int2 d = ((const int2*)(ei + EE))[i];
        atomicAdd(&g_deg[d.x], 1);
        atomicAdd(&g_deg[d.y], 1);
    }

    // fill xs: 4096 float4, 8 per thread
#pragma unroll
    for (int i = 0; i < 8; i++) {
        int idx4 = tid + i * 512;
        int row = idx4 >> 5, kq = idx4 & 31;
        float4 v = make_float4(0, 0, 0, 0);
        if (n0 + row < NN) v = *(const float4*)(x + (size_t)(n0 + row) * 128 + kq * 4);
        *(float4*)&xs[row][kq * 4] = v;
    }

    // prefetch kt=0 W slab
    int pkk = tid >> 6, pcc = (tid & 63) * 4;
    float4 pre = *(const float4*)(Wf + (size_t)pkk * 256 + pcc);
    *(float4*)&Bs[0][pkk][pcc] = pre;

    float4 asA = *(const float4*)(a_s + tx * 4);
    float4 asB = *(const float4*)(a_s + 128 + tx * 4);
    float4 adA = *(const float4*)(a_d + tx * 4);
    float4 adB = *(const float4*)(a_d + 128 + tx * 4);

    ull accp[8][4];
#pragma unroll
    for (int i = 0; i < 8; i++)
#pragma unroll
        for (int j = 0; j < 4; j++) accp[i][j] = 0ull;

    __syncthreads();

    for (int kt = 0; kt < 16; kt++) {
        if (kt < 15)
            pre = *(const float4*)(Wf + (size_t)((kt + 1) * 8 + pkk) * 256 + pcc);
        const float (*B)[256] = Bs[kt & 1];
#pragma unroll
        for (int half = 0; half < 2; half++) {
            {
                ull b[4][2];
#pragma unroll
                for (int kk = 0; kk < 4; kk++) {
                    float4 t = *(const float4*)&B[half * 4 + kk][tx * 4];
                    b[kk][0] = pk2(t.x, t.y); b[kk][1] = pk2(t.z, t.w);
                }
#pragma unroll
                for (int i = 0; i < 8; i++) {
                    float4 af = *(const float4*)&xs[ty * 8 + i][kt * 8 + half * 4];
                    ull a0 = pk2(af.x, af.x), a1 = pk2(af.y, af.y);
                    ull a2 = pk2(af.z, af.z), a3 = pk2(af.w, af.w);
                    FMA2(accp[i][0], a0, b[0][0]); FMA2(accp[i][1], a0, b[0][1]);
                    FMA2(accp[i][0], a1, b[1][0]); FMA2(accp[i][1], a1, b[1][1]);
                    FMA2(accp[i][0], a2, b[2][0]); FMA2(accp[i][1], a2, b[2][1]);
                    FMA2(accp[i][0], a3, b[3][0]); FMA2(accp[i][1], a3, b[3][1]);
                }
            }
            {
                ull b[4][2];
#pragma unroll
                for (int kk = 0; kk < 4; kk++) {
                    float4 t = *(const float4*)&B[half * 4 + kk][128 + tx * 4];
                    b[kk][0] = pk2(t.x, t.y); b[kk][1] = pk2(t.z, t.w);
                }
#pragma unroll
                for (int i = 0; i < 8; i++) {
                    float4 af = *(const float4*)&xs[ty * 8 + i][kt * 8 + half * 4];
                    ull a0 = pk2(af.x, af.x), a1 = pk2(af.y, af.y);
                    ull a2 = pk2(af.z, af.z), a3 = pk2(af.w, af.w);
                    FMA2(accp[i][2], a0, b[0][0]); FMA2(accp[i][3], a0, b[0][1]);
                    FMA2(accp[i][2], a1, b[1][0]); FMA2(accp[i][3], a1, b[1][1]);
                    FMA2(accp[i][2], a2, b[2][0]); FMA2(accp[i][3], a2, b[2][1]);
                    FMA2(accp[i][2], a3, b[3][0]); FMA2(accp[i][3], a3, b[3][1]);
                }
            }
        }
        if (kt < 15) {
            *(float4*)&Bs[(kt + 1) & 1][pkk][pcc] = pre;
            __syncthreads();
        }
    }

    // epilogue: store hfeat + fused attention-logit dots
#pragma unroll
    for (int i = 0; i < 8; i++) {
        int row = n0 + ty * 8 + i;
        bool ok = row < NN;
        float4 vA, vB;
        upk2(accp[i][0], vA.x, vA.y); upk2(accp[i][1], vA.z, vA.w);
        upk2(accp[i][2], vB.x, vB.y); upk2(accp[i][3], vB.z, vB.w);
        if (ok) {
            *(float4*)(g_hfeat + (size_t)row * 256 + tx * 4)       = vA;
            *(float4*)(g_hfeat + (size_t)row * 256 + 128 + tx * 4) = vB;
        }
        float psA = vA.x * asA.x + vA.y * asA.y + vA.z * asA.z + vA.w * asA.w;
        float psB = vB.x * asB.x + vB.y * asB.y + vB.z * asB.z + vB.w * asB.w;
        float pdA = vA.x * adA.x + vA.y * adA.y + vA.z * adA.z + vA.w * adA.w;
        float pdB = vB.x * adB.x + vB.y * adB.y + vB.z * adB.z + vB.w * adB.w;
        for (int o = 1; o < 16; o <<= 1) {
            psA += __shfl_xor_sync(~0u, psA, o);
            psB += __shfl_xor_sync(~0u, psB, o);
            pdA += __shfl_xor_sync(~0u, pdA, o);
            pdB += __shfl_xor_sync(~0u, pdB, o);
        }
        if ((tx & 15) == 0 && ok) {
            int hA = tx >> 4;
            g_als[row * 4 + hA]     = psA;
            g_als[row * 4 + 2 + hA] = psB;
            g_ald[row * 4 + hA]     = pdA;
            g_ald[row * 4 + 2 + hA] = pdB;
        }
    }
}

// ------------------- big conv: warp per dst node, packed smem alphas, ull2 gather, streaming out -------------------
__global__ __launch_bounds__(128) void k_conv1(
    const float* __restrict__ b_feat, const float* __restrict__ W_mlp,
    const float* __restrict__ b_mlp, float* __restrict__ out) {
    __shared__ int ss[4][32];
    __shared__ ull spd[4][32][4];       // per-edge duplicated alphas: [p0p0, p1p1, p2p2, p3p3]
    int w = threadIdx.x >> 5;
    int gwarp = (blockIdx.x * blockDim.x + threadIdx.x) >> 5;
    int lane = threadIdx.x & 31;
    if (gwarp >= NN) return;
    int n = gwarp;
    int beg = g_rowptr[n], end = g_rowptr[n + 1];

    const float4* als4 = (const float4*)g_als;
    float4 ad = ((const float4*)g_ald)[n];
    int selA = (lane >> 4) & 1;         // head within group pair

    float s0 = 0.f, s1 = 0.f, s2 = 0.f, s3 = 0.f;
    ull acc0 = 0, acc1 = 0, acc2 = 0, acc3 = 0;

    for (int base = beg; base < end; base += 32) {
        int idx = base + lane;
        int sl = 0;
        float p0 = 0.f, p1 = 0.f, p2 = 0.f, p3 = 0.f;
        if (idx < end) {
            sl = ldcs_i(g_srt + idx);
            float4 as = als4[sl];
            p0 = __expf(lrelu(as.x + ad.x));
            p1 = __expf(lrelu(as.y + ad.y));
            p2 = __expf(lrelu(as.z + ad.z));
            p3 = __expf(lrelu(as.w + ad.w));
            s0 += p0; s1 += p1; s2 += p2; s3 += p3;
        }
        __syncwarp();
        ss[w][lane] = sl;
        spd[w][lane][0] = pk2(p0, p0);
        spd[w][lane][1] = pk2(p1, p1);
        spd[w][lane][2] = pk2(p2, p2);
        spd[w][lane][3] = pk2(p3, p3);
        __syncwarp();
        int cnt = min(32, end - base);
        int j = 0;
#pragma unroll 1
        for (; j + 2 <= cnt; j += 2) {
            int sb0 = ss[w][j], sb1 = ss[w][j + 1];
            ull aA0 = spd[w][j][selA],     aB0 = spd[w][j][2 + selA];
            ull aA1 = spd[w][j + 1][selA], aB1 = spd[w][j + 1][2 + selA];
            const ulonglong2* hr0 = (const ulonglong2*)(g_hfeat + (size_t)sb0 * 256);
            const ulonglong2* hr1 = (const ulonglong2*)(g_hfeat + (size_t)sb1 * 256);
            ulonglong2 hA0 = hr0[lane], hB0 = hr0[lane + 32];
            ulonglong2 hA1 = hr1[lane], hB1 = hr1[lane + 32];
            FMA2(acc0, aA0, hA0.x); FMA2(acc1, aA0, hA0.y);
            FMA2(acc2, aB0, hB0.x); FMA2(acc3, aB0, hB0.y);
            FMA2(acc0, aA1, hA1.x); FMA2(acc1, aA1, hA1.y);
            FMA2(acc2, aB1, hB1.x); FMA2(acc3, aB1, hB1.y);
        }
        if (j < cnt) {
            int sb = ss[w][j];
            ull aA = spd[w][j][selA], aB = spd[w][j][2 + selA];
            const ulonglong2* hr = (const ulonglong2*)(g_hfeat + (size_t)sb * 256);
            ulonglong2 hA = hr[lane], hB = hr[lane + 32];
            FMA2(acc0, aA, hA.x); FMA2(acc1, aA, hA.y);
            FMA2(acc2, aB, hB.x); FMA2(acc3, aB, hB.y);
        }
    }

    for (int o = 16; o; o >>= 1) {
        s0 += __shfl_xor_sync(~0u, s0, o);
        s1 += __shfl_xor_sync(~0u, s1, o);
        s2 += __shfl_xor_sync(~0u, s2, o);
        s3 += __shfl_xor_sync(~0u, s3, o);
    }
    float i0 = 1.f / (s0 + 1e-16f), i1 = 1.f / (s1 + 1e-16f);
    float i2 = 1.f / (s2 + 1e-16f), i3 = 1.f / (s3 + 1e-16f);
    float invA = selA ? i1 : i0;
    float invB = selA ? i3 : i2;

    float a0, a1, a2, a3, b0, b1, b2, b3;
    upk2(acc0, a0, a1); upk2(acc1, a2, a3);
    upk2(acc2, b0, b1); upk2(acc3, b2, b3);
    float4 bfA = *(const float4*)(b_feat + 4 * lane);
    float4 bfB = *(const float4*)(b_feat + 128 + 4 * lane);
    float heA0 = eluf(a0 * invA + bfA.x), heA1 = eluf(a1 * invA + bfA.y);
    float heA2 = eluf(a2 * invA + bfA.z), heA3 = eluf(a3 * invA + bfA.w);
    float heB0 = eluf(b0 * invB + bfB.x), heB1 = eluf(b1 * invB + bfB.y);
    float heB2 = eluf(b2 * invB + bfB.z), heB3 = eluf(b3 * invB + bfB.w);
    *(float4*)(g_h1 + (size_t)n * 256 + 4 * lane)       = make_float4(heA0, heA1, heA2, heA3);
    *(float4*)(g_h1 + (size_t)n * 256 + 128 + 4 * lane) = make_float4(heB0, heB1, heB2, heB3);

    float4 wA0 = *(const float4*)(W_mlp + 8 * lane);
    float4 wA1 = *(const float4*)(W_mlp + 8 * lane + 4);
    float4 wB0 = *(const float4*)(W_mlp + 256 + 8 * lane);
    float4 wB1 = *(const float4*)(W_mlp + 256 + 8 * lane + 4);
    float l0 = heA0 * wA0.x + heA1 * wA0.z + heA2 * wA1.x + heA3 * wA1.z
             + heB0 * wB0.x + heB1 * wB0.z + heB2 * wB1.x + heB3 * wB1.z;
    float l1 = heA0 * wA0.y + heA1 * wA0.w + heA2 * wA1.y + heA3 * wA1.w
             + heB0 * wB0.y + heB1 * wB0.w + heB2 * wB1.y + heB3 * wB1.w;
    for (int o = 16; o; o >>= 1) {
        l0 += __shfl_xor_sync(~0u, l0, o);
        l1 += __shfl_xor_sync(~0u, l1, o);
    }
    l0 += b_mlp[0];
    l1 += b_mlp[1];
    float mm = fmaxf(l0, l1);
    float e0 = __expf(l0 - mm), e1 = __expf(l1 - mm);
    float inv2 = 1.f / (e0 + e1);
    float att0 = e0 * inv2, att1 = e1 * inv2;
    if (lane == 0) g_att[n] = make_float2(att0, att1);

    stcs4(out + O3 + (size_t)n * 256 + 4 * lane,
          make_float4(eluf(att0 * heA0), eluf(att0 * heA1), eluf(att0 * heA2), eluf(att0 * heA3)));
    stcs4(out + O3 + (size_t)n * 256 + 128 + 4 * lane,
          make_float4(eluf(att0 * heB0), eluf(att0 * heB1), eluf(att0 * heB2), eluf(att0 * heB3)));
    stcs4(out + O4 + (size_t)n * 256 + 4 * lane,
          make_float4(eluf(att1 * heA0), eluf(att1 * heA1), eluf(att1 * heA2), eluf(att1 * heA3)));
    stcs4(out + O4 + (size_t)n * 256 + 128 + 4 * lane,
          make_float4(eluf(att1 * heB0), eluf(att1 * heB1), eluf(att1 * heB2), eluf(att1 * heB3)));
}

// ------------------- GEMM2: Y = h1 @ [Wobj|Wctx|Wco] (att-scaled), + logit dots, f32x2 -------------------
__global__ __launch_bounds__(256) void k_gemm2(
    const float* __restrict__ Wo, const float* __restrict__ Wc, const float* __restrict__ Wx,
    const float* __restrict__ aso, const float* __restrict__ ado,
    const float* __restrict__ asc, const float* __restrict__ adc,
    const float* __restrict__ asx, const float* __restrict__ adx) {
    __shared__ float sh[16][266];   // 1064B stride: 8-aligned only — float2/ull access
    __shared__ float ws[16][266];
    __shared__ float ysm[16][52];
    int tid = threadIdx.x;
    int n0 = blockIdx.x * 16;

#pragma unroll
    for (int i = 0; i < 8; i++) {
        int idx2 = tid + i * 256;
        int row = idx2 >> 7, kq = idx2 & 127;
        *(float2*)&sh[row][kq * 2] = *(const float2*)(g_h1 + (size_t)(n0 + row) * 256 + kq * 2);
    }

    int node = tid >> 4, c = tid & 15;
    float2 att = g_att[n0 + node];

    for (int v = 0; v < 3; v++) {
        const float* W = (v == 0) ? Wo : (v == 1) ? Wc : Wx;
        float scale = (v == 0) ? att.x : (v == 1) ? att.y : 1.f;
        __syncthreads();
#pragma unroll
        for (int i = 0; i < 16; i++) {
            int idx = tid + i * 256;
            ws[idx & 15][idx >> 4] = W[idx];
        }
        __syncthreads();
        const ull* h2 = (const ull*)&sh[node][0];
        const ull* w2 = (const ull*)&ws[c][0];
        ull ap = 0ull;
#pragma unroll 16
        for (int k = 0; k < 128; k++) FMA2(ap, h2[k], w2[k]);
        float lo, hi;
        upk2(ap, lo, hi);
        float y = (lo + hi) * scale;
        g_gall[(size_t)(n0 + node) * 48 + v * 16 + c] = y;
        ysm[node][v * 16 + c] = y;
    }
    __syncthreads();
    if (tid < 192) {
        int nd = tid / 12, r = tid % 12;
        int v = r >> 2, h = (r >> 1) & 1, sd = r & 1;
        const float* a = sd ? ((v == 0) ? ado : (v == 1) ? adc : adx)
                            : ((v == 0) ? aso : (v == 1) ? asc : asx);
        float s = 0.f;
#pragma unroll
        for (int o = 0; o < 8; o++) s += ysm[nd][v * 16 + h * 8 + o] * a[h * 8 + o];
        float* dstp = sd ? g_aldP : g_alsP;
        dstp[(n0 + nd) * 8 + v * 2 + h] = s;
    }
}

// ------------------- merged small convs: warp per dst node, packed smem p's, streaming out -------------------
__global__ __launch_bounds__(128) void k_conv2m(
    const float* __restrict__ b_obj, const float* __restrict__ b_ctx,
    const float* __restrict__ b_co, float* __restrict__ out) {
    __shared__ int   ss[4][32];
    __shared__ float sp6[4][32][8];     // 6 p's per edge (padded to 8)
    int w = threadIdx.x >> 5;
    int gwarp = (blockIdx.x * blockDim.x + threadIdx.x) >> 5;
    int lane = threadIdx.x & 31;
    if (gwarp >= NN) return;
    int n = gwarp;
    int beg = g_rowptr[n], end = g_rowptr[n + 1];

    float4 dA = *(const float4*)(g_aldP + n * 8);
    float2 dB = *(const float2*)(g_aldP + n * 8 + 4);
    float ald[6] = {dA.x, dA.y, dA.z, dA.w, dB.x, dB.y};

    int sub = lane & 15;
    int hh = (lane >> 3) & 1;
    float s[6] = {0, 0, 0, 0, 0, 0};
    float acc0 = 0.f, acc1 = 0.f, acc2 = 0.f;

    for (int base = beg; base < end; base += 32) {
        int idx = base + lane;
        int sl = 0;
        float p[6] = {0, 0, 0, 0, 0, 0};
        if (idx < end) {
            sl = ldcs_i(g_srt + idx);
            float4 sA = *(const float4*)(g_alsP + sl * 8);
            float2 sB = *(const float2*)(g_alsP + sl * 8 + 4);
            float als[6] = {sA.x, sA.y, sA.z, sA.w, sB.x, sB.y};
#pragma unroll
            for (int k = 0; k < 6; k++) {
                p[k] = __expf(lrelu(als[k] + ald[k]));
                s[k] += p[k];
            }
        }
        __syncwarp();
        ss[w][lane] = sl;
#pragma unroll
        for (int k = 0; k < 6; k++) sp6[w][lane][k] = p[k];
        __syncwarp();
        int cnt = min(32, end - base);
        int j = 0;
#pragma unroll 1
        for (; j + 2 <= cnt; j += 2) {
            int sb0 = ss[w][j], sb1 = ss[w][j + 1];
            float q00 = sp6[w][j][hh],     q01 = sp6[w][j][2 + hh],     q02 = sp6[w][j][4 + hh];
            float q10 = sp6[w][j + 1][hh], q11 = sp6[w][j + 1][2 + hh], q12 = sp6[w][j + 1][4 + hh];
            const float* g0 = g_gall + (size_t)sb0 * 48;
            const float* g1 = g_gall + (size_t)sb1 * 48;
            acc0 += q00 * g0[sub] + q10 * g1[sub];
            acc1 += q01 * g0[16 + sub] + q11 * g1[16 + sub];
            acc2 += q02 * g0[32 + sub] + q12 * g1[32 + sub];
        }
        if (j < cnt) {
            int sb = ss[w][j];
            float q0 = sp6[w][j][hh], q1 = sp6[w][j][2 + hh], q2 = sp6[w][j][4 + hh];
            const float* gr = g_gall + (size_t)sb * 48;
            acc0 += q0 * gr[sub];
            acc1 += q1 * gr[16 + sub];
            acc2 += q2 * gr[32 + sub];
        }
    }

    for (int o = 16; o; o >>= 1) {
#pragma unroll
        for (int k = 0; k < 6; k++) s[k] += __shfl_xor_sync(~0u, s[k], o);
    }
    acc0 *= 1.f / (s[hh] + 1e-16f);
    acc1 *= 1.f / (s[2 + hh] + 1e-16f);
    acc2 *= 1.f / (s[4 + hh] + 1e-16f);

    float v0 = 0.5f * (acc0 + __shfl_xor_sync(~0u, acc0, 8)) + b_obj[lane & 7];
    float v1 = 0.5f * (acc1 + __shfl_xor_sync(~0u, acc1, 8)) + b_ctx[lane & 7];
    float v2 = 0.5f * (acc2 + __shfl_xor_sync(~0u, acc2, 8)) + b_co[lane & 7];
    float mv0 = v0, mv1 = v1, mv2 = v2;
    for (int o = 4; o; o >>= 1) {
        mv0 = fmaxf(mv0, __shfl_xor_sync(~0u, mv0, o, 8));
        mv1 = fmaxf(mv1, __shfl_xor_sync(~0u, mv1, o, 8));
        mv2 = fmaxf(mv2, __shfl_xor_sync(~0u, mv2, o, 8));
    }
    float se0 = __expf(v0 - mv0), se1 = __expf(v1 - mv1), se2 = __expf(v2 - mv2);
    for (int o = 4; o; o >>= 1) {
        se0 += __shfl_xor_sync(~0u, se0, o, 8);
        se1 += __shfl_xor_sync(~0u, se1, o, 8);
        se2 += __shfl_xor_sync(~0u, se2, o, 8);
    }
    if (lane < 8) {
        stcs1(out + O0 + (size_t)n * 8 + lane, v0 - mv0 - logf(se0));
        stcs1(out + O1 + (size_t)n * 8 + lane, v1 - mv1 - logf(se1));
        stcs1(out + O2 + (size_t)n * 8 + lane, v2 - mv2 - logf(se2));
    }
}

// ------------------- launch -------------------
extern "C" void kernel_launch(void* const* d_in, const int* in_sizes, int n_in,
                              void* d_out, int out_size) {
    const float* x      = (const float*)d_in[0];
    const int*   ei     = (const int*)d_in[1];
    const float* W_feat = (const float*)d_in[2];
    const float* a_s_f  = (const float*)d_in[3];
    const float* a_d_f  = (const float*)d_in[4];
    const float* b_feat = (const float*)d_in[5];
    const float* W_mlp  = (const float*)d_in[6];
    const float* b_mlp  = (const float*)d_in[7];
    const float* W_obj  = (const float*)d_in[8];
    const float* a_s_o  = (const float*)d_in[9];
    const float* a_d_o  = (const float*)d_in[10];
    const float* b_obj  = (const float*)d_in[11];
    const float* W_ctx  = (const float*)d_in[12];
    const float* a_s_c  = (const float*)d_in[13];
    const float* a_d_c  = (const float*)d_in[14];
    const float* b_ctx  = (const float*)d_in[15];
    const float* W_co   = (const float*)d_in[16];
    const float* a_s_x  = (const float*)d_in[17];
    const float* a_d_x  = (const float*)d_in[18];
    const float* b_co   = (const float*)d_in[19];
    float* out = (float*)d_out;

    const int GEMM1_SMEM = 128 * 128 * 4 + 2 * 8 * 256 * 4;   // 81920 B
    cudaFuncSetAttribute(k_gemm1, cudaFuncAttributeMaxDynamicSharedMemorySize, GEMM1_SMEM);

    // order: conv1 is the 4th launch (ncu capture slot)
    k_gemm1<<<NB1, 512, GEMM1_SMEM>>>(x, W_feat, a_s_f, a_d_f, ei);   // fused hist
    k_scan<<<1, 1024>>>();
    k_scatter<<<(EE / 2 + NN + 255) / 256, 256>>>(ei);
    k_conv1<<<(NN + 3) / 4, 128>>>(b_feat, W_mlp, b_mlp, out);

    k_gemm2<<<NN / 16, 256>>>(W_obj, W_ctx, W_co,
                              a_s_o, a_d_o, a_s_c, a_d_c, a_s_x, a_d_x);
    k_conv2m<<<(NN + 3) / 4, 128>>>(b_obj, b_ctx, b_co, out);
}

// round 14
// speedup vs baseline: 1.0580x; 1.0580x over previous
#include <cuda_runtime.h>
#include <cstdint>

#define NN 50000
#define EE 800000
#define ET (EE + NN)
#define NB1 391                       // gemm1 blocks: ceil(50000/128)

// output layout: xo_logis [N,8] | xc_logis [N,8] | xco_logis [N,8] | elu(xo) [N,256] | elu(xc) [N,256]
#define O0 0
#define O1 (NN*8)
#define O2 (2*NN*8)
#define O3 (3*NN*8)
#define O4 (3*NN*8 + NN*256)

typedef unsigned long long ull;

__device__ __forceinline__ ull pk2(float lo, float hi) {
    ull r; asm("mov.b64 %0, {%1, %2};" : "=l"(r) : "f"(lo), "f"(hi)); return r;
}
__device__ __forceinline__ void upk2(ull v, float& lo, float& hi) {
    asm("mov.b64 {%0, %1}, %2;" : "=f"(lo), "=f"(hi) : "l"(v));
}
#define FMA2(d, a, b) asm("fma.rn.f32x2 %0, %1, %2, %0;" : "+l"(d) : "l"(a), "l"(b))

__device__ __forceinline__ void stcs4(float* p, float4 v) {
    asm volatile("st.global.cs.v4.f32 [%0], {%1,%2,%3,%4};" :: "l"(p),
                 "f"(v.x), "f"(v.y), "f"(v.z), "f"(v.w) : "memory");
}
__device__ __forceinline__ void stcs1(float* p, float v) {
    asm volatile("st.global.cs.f32 [%0], %1;" :: "l"(p), "f"(v) : "memory");
}

// ------------------- static scratch (zero-initialized at module load) -------------------
__device__ int   g_deg[NN];          // ALWAYS zero at kernel_launch entry (scan re-zeroes)
__device__ int   g_rowptr[NN + 1];
__device__ int   g_wptr[NN];
__device__ int   g_srt[ET];

__device__ __align__(16) float  g_hfeat[(size_t)NN * 256];
__device__ __align__(16) float  g_h1[(size_t)NN * 256];
__device__ __align__(16) float2 g_att[NN];

__device__ __align__(16) float g_als[NN * 4], g_ald[NN * 4];
__device__ __align__(16) float g_gall[(size_t)NN * 48];
__device__ __align__(16) float g_alsP[NN * 8], g_aldP[NN * 8];

__device__ __forceinline__ float lrelu(float v) { return v > 0.f ? v : 0.2f * v; }
// fast ELU: MUFU-based exp instead of the ~20-instr expm1f software sequence
__device__ __forceinline__ float eluf(float v)  { return v > 0.f ? v : __expf(v) - 1.f; }

// ------------------- CSR scan + scatter -------------------
__global__ void k_scan() {
    __shared__ int sums[1024];
    int tid = threadIdx.x;
    const int chunk = (NN + 1023) / 1024;
    int start = tid * chunk;
    int s = 0;
    for (int i = 0; i < chunk; i++) {
        int idx = start + i;
        if (idx < NN) s += g_deg[idx] + 1;   // +1 = self loop
    }
    sums[tid] = s;
    __syncthreads();
    for (int off = 1; off < 1024; off <<= 1) {
        int v = 0;
        if (tid >= off) v = sums[tid - off];
        __syncthreads();
        if (tid >= off) sums[tid] += v;
        __syncthreads();
    }
    int prefix = (tid == 0) ? 0 : sums[tid - 1];
    for (int i = 0; i < chunk; i++) {
        int idx = start + i;
        if (idx < NN) {
            g_rowptr[idx] = prefix;
            g_wptr[idx] = prefix;
            prefix += g_deg[idx] + 1;
            g_deg[idx] = 0;                  // restore invariant for next call
        }
    }
    if (tid == 0) g_rowptr[NN] = sums[1023];
}

__global__ void k_scatter(const int* __restrict__ ei) {
    int i = blockIdx.x * blockDim.x + threadIdx.x;
    if (i < EE / 2) {
        int2 s2 = ((const int2*)ei)[i];
        int2 d2 = ((const int2*)(ei + EE))[i];
        int p0 = atomicAdd(&g_wptr[d2.x], 1);
        g_srt[p0] = s2.x;
        int p1 = atomicAdd(&g_wptr[d2.y], 1);
        g_srt[p1] = s2.y;
    } else if (i < EE / 2 + NN) {
        int n = i - EE / 2;
        int pos = atomicAdd(&g_wptr[n], 1);
        g_srt[pos] = n;                      // self loop
    }
}

// ------------------- GEMM1: 128x256 tile, 512 thr, thread = 8 rows x (4+4 cols), fused hist -------------------
__global__ __launch_bounds__(512) void k_gemm1(
    const float* __restrict__ x, const float* __restrict__ Wf,
    const float* __restrict__ a_s, const float* __restrict__ a_d,
    const int* __restrict__ ei) {
    extern __shared__ float smem[];
    float (*xs)[128] = (float (*)[128])smem;                        // 128 x 128 = 64 KB
    float (*Bs)[8][256] = (float (*)[8][256])(smem + 128 * 128);    // [2][8][256] = 16 KB
    int tid = threadIdx.x;
    int n0 = blockIdx.x * 128;
    int ty = tid >> 5, tx = tid & 31;       // ty 0..15 -> 8-row group

    // fused edge histogram (independent of GEMM data flow)
    for (int i = blockIdx.x * 512 + tid; i < EE / 2; i += NB1 * 512) {
        int2 d = ((const int2*)(ei + EE))[i];
        atomicAdd(&g_deg[d.x], 1);
        atomicAdd(&g_deg[d.y], 1);
    }

    // fill xs: 4096 float4, 8 per thread
#pragma unroll
    for (int i = 0; i < 8; i++) {
        int idx4 = tid + i * 512;
        int row = idx4 >> 5, kq = idx4 & 31;
        float4 v = make_float4(0, 0, 0, 0);
        if (n0 + row < NN) v = *(const float4*)(x + (size_t)(n0 + row) * 128 + kq * 4);
        *(float4*)&xs[row][kq * 4] = v;
    }

    // prefetch kt=0 W slab
    int pkk = tid >> 6, pcc = (tid & 63) * 4;
    float4 pre = *(const float4*)(Wf + (size_t)pkk * 256 + pcc);
    *(float4*)&Bs[0][pkk][pcc] = pre;

    float4 asA = *(const float4*)(a_s + tx * 4);
    float4 asB = *(const float4*)(a_s + 128 + tx * 4);
    float4 adA = *(const float4*)(a_d + tx * 4);
    float4 adB = *(const float4*)(a_d + 128 + tx * 4);

    ull accp[8][4];
#pragma unroll
    for (int i = 0; i < 8; i++)
#pragma unroll
        for (int j = 0; j < 4; j++) accp[i][j] = 0ull;

    __syncthreads();

    for (int kt = 0; kt < 16; kt++) {
        if (kt < 15)
            pre = *(const float4*)(Wf + (size_t)((kt + 1) * 8 + pkk) * 256 + pcc);
        const float (*B)[256] = Bs[kt & 1];
#pragma unroll
        for (int half = 0; half < 2; half++) {
            {
                ull b[4][2];
#pragma unroll
                for (int kk = 0; kk < 4; kk++) {
                    float4 t = *(const float4*)&B[half * 4 + kk][tx * 4];
                    b[kk][0] = pk2(t.x, t.y); b[kk][1] = pk2(t.z, t.w);
                }
#pragma unroll
                for (int i = 0; i < 8; i++) {
                    float4 af = *(const float4*)&xs[ty * 8 + i][kt * 8 + half * 4];
                    ull a0 = pk2(af.x, af.x), a1 = pk2(af.y, af.y);
                    ull a2 = pk2(af.z, af.z), a3 = pk2(af.w, af.w);
                    FMA2(accp[i][0], a0, b[0][0]); FMA2(accp[i][1], a0, b[0][1]);
                    FMA2(accp[i][0], a1, b[1][0]); FMA2(accp[i][1], a1, b[1][1]);
                    FMA2(accp[i][0], a2, b[2][0]); FMA2(accp[i][1], a2, b[2][1]);
                    FMA2(accp[i][0], a3, b[3][0]); FMA2(accp[i][1], a3, b[3][1]);
                }
            }
            {
                ull b[4][2];
#pragma unroll
                for (int kk = 0; kk < 4; kk++) {
                    float4 t = *(const float4*)&B[half * 4 + kk][128 + tx * 4];
                    b[kk][0] = pk2(t.x, t.y); b[kk][1] = pk2(t.z, t.w);
                }
#pragma unroll
                for (int i = 0; i < 8; i++) {
                    float4 af = *(const float4*)&xs[ty * 8 + i][kt * 8 + half * 4];
                    ull a0 = pk2(af.x, af.x), a1 = pk2(af.y, af.y);
                    ull a2 = pk2(af.z, af.z), a3 = pk2(af.w, af.w);
                    FMA2(accp[i][2], a0, b[0][0]); FMA2(accp[i][3], a0, b[0][1]);
                    FMA2(accp[i][2], a1, b[1][0]); FMA2(accp[i][3], a1, b[1][1]);
                    FMA2(accp[i][2], a2, b[2][0]); FMA2(accp[i][3], a2, b[2][1]);
                    FMA2(accp[i][2], a3, b[3][0]); FMA2(accp[i][3], a3, b[3][1]);
                }
            }
        }
        if (kt < 15) {
            *(float4*)&Bs[(kt + 1) & 1][pkk][pcc] = pre;
            __syncthreads();
        }
    }

    // epilogue: store hfeat + fused attention-logit dots
#pragma unroll
    for (int i = 0; i < 8; i++) {
        int row = n0 + ty * 8 + i;
        bool ok = row < NN;
        float4 vA, vB;
        upk2(accp[i][0], vA.x, vA.y); upk2(accp[i][1], vA.z, vA.w);
        upk2(accp[i][2], vB.x, vB.y); upk2(accp[i][3], vB.z, vB.w);
        if (ok) {
            *(float4*)(g_hfeat + (size_t)row * 256 + tx * 4)       = vA;
            *(float4*)(g_hfeat + (size_t)row * 256 + 128 + tx * 4) = vB;
        }
        float psA = vA.x * asA.x + vA.y * asA.y + vA.z * asA.z + vA.w * asA.w;
        float psB = vB.x * asB.x + vB.y * asB.y + vB.z * asB.z + vB.w * asB.w;
        float pdA = vA.x * adA.x + vA.y * adA.y + vA.z * adA.z + vA.w * adA.w;
        float pdB = vB.x * adB.x + vB.y * adB.y + vB.z * adB.z + vB.w * adB.w;
        for (int o = 1; o < 16; o <<= 1) {
            psA += __shfl_xor_sync(~0u, psA, o);
            psB += __shfl_xor_sync(~0u, psB, o);
            pdA += __shfl_xor_sync(~0u, pdA, o);
            pdB += __shfl_xor_sync(~0u, pdB, o);
        }
        if ((tx & 15) == 0 && ok) {
            int hA = tx >> 4;
            g_als[row * 4 + hA]     = psA;
            g_als[row * 4 + 2 + hA] = psB;
            g_ald[row * 4 + hA]     = pdA;
            g_ald[row * 4 + 2 + hA] = pdB;
        }
    }
}

// ------------------- big conv: warp per dst node, single pass, unrolled LDG.128 gather -------------------
__global__ __launch_bounds__(128) void k_conv1(
    const float* __restrict__ b_feat, const float* __restrict__ W_mlp,
    const float* __restrict__ b_mlp, float* __restrict__ out) {
    __shared__ int    ss[4][32];
    __shared__ float4 sp[4][32];
    int w = threadIdx.x >> 5;
    int gwarp = (blockIdx.x * blockDim.x + threadIdx.x) >> 5;
    int lane = threadIdx.x & 31;
    if (gwarp >= NN) return;
    int n = gwarp;
    int beg = g_rowptr[n], end = g_rowptr[n + 1];

    const float4* als4 = (const float4*)g_als;
    float4 ad = ((const float4*)g_ald)[n];
    bool lo16 = lane < 16;

    float s0 = 0.f, s1 = 0.f, s2 = 0.f, s3 = 0.f;
    ull acc0 = 0, acc1 = 0, acc2 = 0, acc3 = 0;

    for (int base = beg; base < end; base += 32) {
        int idx = base + lane;
        int sl = 0;
        float4 pv = make_float4(0, 0, 0, 0);
        if (idx < end) {
            sl = g_srt[idx];
            float4 as = als4[sl];
            pv.x = __expf(lrelu(as.x + ad.x));
            pv.y = __expf(lrelu(as.y + ad.y));
            pv.z = __expf(lrelu(as.z + ad.z));
            pv.w = __expf(lrelu(as.w + ad.w));
            s0 += pv.x; s1 += pv.y; s2 += pv.z; s3 += pv.w;
        }
        __syncwarp();
        ss[w][lane] = sl;
        sp[w][lane] = pv;
        __syncwarp();
        int cnt = min(32, end - base);
        int j = 0;
#pragma unroll 1
        for (; j + 2 <= cnt; j += 2) {
            int sb0 = ss[w][j], sb1 = ss[w][j + 1];
            float4 pj0 = sp[w][j], pj1 = sp[w][j + 1];
            const float4* hr0 = (const float4*)(g_hfeat + (size_t)sb0 * 256);
            const float4* hr1 = (const float4*)(g_hfeat + (size_t)sb1 * 256);
            float4 hA0 = hr0[lane], hB0 = hr0[lane + 32];
            float4 hA1 = hr1[lane], hB1 = hr1[lane + 32];
            float aA0 = lo16 ? pj0.x : pj0.y, aB0 = lo16 ? pj0.z : pj0.w;
            float aA1 = lo16 ? pj1.x : pj1.y, aB1 = lo16 ? pj1.z : pj1.w;
            ull aA0p = pk2(aA0, aA0), aB0p = pk2(aB0, aB0);
            ull aA1p = pk2(aA1, aA1), aB1p = pk2(aB1, aB1);
            FMA2(acc0, aA0p, pk2(hA0.x, hA0.y));
            FMA2(acc1, aA0p, pk2(hA0.z, hA0.w));
            FMA2(acc2, aB0p, pk2(hB0.x, hB0.y));
            FMA2(acc3, aB0p, pk2(hB0.z, hB0.w));
            FMA2(acc0, aA1p, pk2(hA1.x, hA1.y));
            FMA2(acc1, aA1p, pk2(hA1.z, hA1.w));
            FMA2(acc2, aB1p, pk2(hB1.x, hB1.y));
            FMA2(acc3, aB1p, pk2(hB1.z, hB1.w));
        }
        if (j < cnt) {
            int sb = ss[w][j];
            float4 pj = sp[w][j];
            const float4* hr4 = (const float4*)(g_hfeat + (size_t)sb * 256);
            float4 hA = hr4[lane], hB = hr4[lane + 32];
            float aA = lo16 ? pj.x : pj.y, aB = lo16 ? pj.z : pj.w;
            ull aAp = pk2(aA, aA), aBp = pk2(aB, aB);
            FMA2(acc0, aAp, pk2(hA.x, hA.y));
            FMA2(acc1, aAp, pk2(hA.z, hA.w));
            FMA2(acc2, aBp, pk2(hB.x, hB.y));
            FMA2(acc3, aBp, pk2(hB.z, hB.w));
        }
    }

    for (int o = 16; o; o >>= 1) {
        s0 += __shfl_xor_sync(~0u, s0, o);
        s1 += __shfl_xor_sync(~0u, s1, o);
        s2 += __shfl_xor_sync(~0u, s2, o);
        s3 += __shfl_xor_sync(~0u, s3, o);
    }
    float i0 = 1.f / (s0 + 1e-16f), i1 = 1.f / (s1 + 1e-16f);
    float i2 = 1.f / (s2 + 1e-16f), i3 = 1.f / (s3 + 1e-16f);
    float invA = lo16 ? i0 : i1;
    float invB = lo16 ? i2 : i3;

    float a0, a1, a2, a3, b0, b1, b2, b3;
    upk2(acc0, a0, a1); upk2(acc1, a2, a3);
    upk2(acc2, b0, b1); upk2(acc3, b2, b3);
    float4 bfA = *(const float4*)(b_feat + 4 * lane);
    float4 bfB = *(const float4*)(b_feat + 128 + 4 * lane);
    float heA0 = eluf(a0 * invA + bfA.x), heA1 = eluf(a1 * invA + bfA.y);
    float heA2 = eluf(a2 * invA + bfA.z), heA3 = eluf(a3 * invA + bfA.w);
    float heB0 = eluf(b0 * invB + bfB.x), heB1 = eluf(b1 * invB + bfB.y);
    float heB2 = eluf(b2 * invB + bfB.z), heB3 = eluf(b3 * invB + bfB.w);
    *(float4*)(g_h1 + (size_t)n * 256 + 4 * lane)       = make_float4(heA0, heA1, heA2, heA3);
    *(float4*)(g_h1 + (size_t)n * 256 + 128 + 4 * lane) = make_float4(heB0, heB1, heB2, heB3);

    float4 wA0 = *(const float4*)(W_mlp + 8 * lane);
    float4 wA1 = *(const float4*)(W_mlp + 8 * lane + 4);
    float4 wB0 = *(const float4*)(W_mlp + 256 + 8 * lane);
    float4 wB1 = *(const float4*)(W_mlp + 256 + 8 * lane + 4);
    float l0 = heA0 * wA0.x + heA1 * wA0.z + heA2 * wA1.x + heA3 * wA1.z
             + heB0 * wB0.x + heB1 * wB0.z + heB2 * wB1.x + heB3 * wB1.z;
    float l1 = heA0 * wA0.y + heA1 * wA0.w + heA2 * wA1.y + heA3 * wA1.w
             + heB0 * wB0.y + heB1 * wB0.w + heB2 * wB1.y + heB3 * wB1.w;
    for (int o = 16; o; o >>= 1) {
        l0 += __shfl_xor_sync(~0u, l0, o);
        l1 += __shfl_xor_sync(~0u, l1, o);
    }
    l0 += b_mlp[0];
    l1 += b_mlp[1];
    float mm = fmaxf(l0, l1);
    float e0 = __expf(l0 - mm), e1 = __expf(l1 - mm);
    float inv2 = 1.f / (e0 + e1);
    float att0 = e0 * inv2, att1 = e1 * inv2;
    if (lane == 0) g_att[n] = make_float2(att0, att1);

    stcs4(out + O3 + (size_t)n * 256 + 4 * lane,
          make_float4(eluf(att0 * heA0), eluf(att0 * heA1), eluf(att0 * heA2), eluf(att0 * heA3)));
    stcs4(out + O3 + (size_t)n * 256 + 128 + 4 * lane,
          make_float4(eluf(att0 * heB0), eluf(att0 * heB1), eluf(att0 * heB2), eluf(att0 * heB3)));
    stcs4(out + O4 + (size_t)n * 256 + 4 * lane,
          make_float4(eluf(att1 * heA0), eluf(att1 * heA1), eluf(att1 * heA2), eluf(att1 * heA3)));
    stcs4(out + O4 + (size_t)n * 256 + 128 + 4 * lane,
          make_float4(eluf(att1 * heB0), eluf(att1 * heB1), eluf(att1 * heB2), eluf(att1 * heB3)));
}

// ------------------- GEMM2: Y = h1 @ [Wobj|Wctx|Wco] (att-scaled), + logit dots, f32x2 -------------------
__global__ __launch_bounds__(256) void k_gemm2(
    const float* __restrict__ Wo, const float* __restrict__ Wc, const float* __restrict__ Wx,
    const float* __restrict__ aso, const float* __restrict__ ado,
    const float* __restrict__ asc, const float* __restrict__ adc,
    const float* __restrict__ asx, const float* __restrict__ adx) {
    __shared__ float sh[16][266];   // 1064B stride: 8-aligned only — float2/ull access
    __shared__ float ws[16][266];
    __shared__ float ysm[16][52];
    int tid = threadIdx.x;
    int n0 = blockIdx.x * 16;

#pragma unroll
    for (int i = 0; i < 8; i++) {
        int idx2 = tid + i * 256;
        int row = idx2 >> 7, kq = idx2 & 127;
        *(float2*)&sh[row][kq * 2] = *(const float2*)(g_h1 + (size_t)(n0 + row) * 256 + kq * 2);
    }

    int node = tid >> 4, c = tid & 15;
    float2 att = g_att[n0 + node];

    for (int v = 0; v < 3; v++) {
        const float* W = (v == 0) ? Wo : (v == 1) ? Wc : Wx;
        float scale = (v == 0) ? att.x : (v == 1) ? att.y : 1.f;
        __syncthreads();
#pragma unroll
        for (int i = 0; i < 16; i++) {
            int idx = tid + i * 256;
            ws[idx & 15][idx >> 4] = W[idx];
        }
        __syncthreads();
        const ull* h2 = (const ull*)&sh[node][0];
        const ull* w2 = (const ull*)&ws[c][0];
        ull ap = 0ull;
#pragma unroll 16
        for (int k = 0; k < 128; k++) FMA2(ap, h2[k], w2[k]);
        float lo, hi;
        upk2(ap, lo, hi);
        float y = (lo + hi) * scale;
        g_gall[(size_t)(n0 + node) * 48 + v * 16 + c] = y;
        ysm[node][v * 16 + c] = y;
    }
    __syncthreads();
    if (tid < 192) {
        int nd = tid / 12, r = tid % 12;
        int v = r >> 2, h = (r >> 1) & 1, sd = r & 1;
        const float* a = sd ? ((v == 0) ? ado : (v == 1) ? adc : adx)
                            : ((v == 0) ? aso : (v == 1) ? asc : asx);
        float s = 0.f;
#pragma unroll
        for (int o = 0; o < 8; o++) s += ysm[nd][v * 16 + h * 8 + o] * a[h * 8 + o];
        float* dstp = sd ? g_aldP : g_alsP;
        dstp[(n0 + nd) * 8 + v * 2 + h] = s;
    }
}

// ------------------- merged small convs: warp per dst node, single pass, unrolled -------------------
__global__ __launch_bounds__(128) void k_conv2m(
    const float* __restrict__ b_obj, const float* __restrict__ b_ctx,
    const float* __restrict__ b_co, float* __restrict__ out) {
    __shared__ int    ss[4][32];
    __shared__ float4 spA[4][32];
    __shared__ float2 spB[4][32];
    int w = threadIdx.x >> 5;
    int gwarp = (blockIdx.x * blockDim.x + threadIdx.x) >> 5;
    int lane = threadIdx.x & 31;
    if (gwarp >= NN) return;
    int n = gwarp;
    int beg = g_rowptr[n], end = g_rowptr[n + 1];

    float4 dA = *(const float4*)(g_aldP + n * 8);
    float2 dB = *(const float2*)(g_aldP + n * 8 + 4);
    float ald[6] = {dA.x, dA.y, dA.z, dA.w, dB.x, dB.y};

    int sub = lane & 15;
    int hh = (lane >> 3) & 1;
    float s[6] = {0, 0, 0, 0, 0, 0};
    float acc0 = 0.f, acc1 = 0.f, acc2 = 0.f;

    for (int base = beg; base < end; base += 32) {
        int idx = base + lane;
        int sl = 0;
        float p[6] = {0, 0, 0, 0, 0, 0};
        if (idx < end) {
            sl = g_srt[idx];
            float4 sA = *(const float4*)(g_alsP + sl * 8);
            float2 sB = *(const float2*)(g_alsP + sl * 8 + 4);
            float als[6] = {sA.x, sA.y, sA.z, sA.w, sB.x, sB.y};
#pragma unroll
            for (int k = 0; k < 6; k++) {
                p[k] = __expf(lrelu(als[k] + ald[k]));
                s[k] += p[k];
            }
        }
        __syncwarp();
        ss[w][lane] = sl;
        spA[w][lane] = make_float4(p[0], p[1], p[2], p[3]);
        spB[w][lane] = make_float2(p[4], p[5]);
        __syncwarp();
        int cnt = min(32, end - base);
        int j = 0;
#pragma unroll 1
        for (; j + 2 <= cnt; j += 2) {
            int sb0 = ss[w][j], sb1 = ss[w][j + 1];
            float4 qA0 = spA[w][j], qA1 = spA[w][j + 1];
            float2 qB0 = spB[w][j], qB1 = spB[w][j + 1];
            const float* g0 = g_gall + (size_t)sb0 * 48;
            const float* g1 = g_gall + (size_t)sb1 * 48;
            float x00 = g0[sub], x01 = g0[16 + sub], x02 = g0[32 + sub];
            float x10 = g1[sub], x11 = g1[16 + sub], x12 = g1[32 + sub];
            acc0 += (hh ? qA0.y : qA0.x) * x00 + (hh ? qA1.y : qA1.x) * x10;
            acc1 += (hh ? qA0.w : qA0.z) * x01 + (hh ? qA1.w : qA1.z) * x11;
            acc2 += (hh ? qB0.y : qB0.x) * x02 + (hh ? qB1.y : qB1.x) * x12;
        }
        if (j < cnt) {
            int sb = ss[w][j];
            float4 qA = spA[w][j];
            float2 qB = spB[w][j];
            const float* gr = g_gall + (size_t)sb * 48;
            acc0 += (hh ? qA.y : qA.x) * gr[sub];
            acc1 += (hh ? qA.w : qA.z) * gr[16 + sub];
            acc2 += (hh ? qB.y : qB.x) * gr[32 + sub];
        }
    }

    for (int o = 16; o; o >>= 1) {
#pragma unroll
        for (int k = 0; k < 6; k++) s[k] += __shfl_xor_sync(~0u, s[k], o);
    }
    acc0 *= 1.f / (s[hh] + 1e-16f);
    acc1 *= 1.f / (s[2 + hh] + 1e-16f);
    acc2 *= 1.f / (s[4 + hh] + 1e-16f);

    float v0 = 0.5f * (acc0 + __shfl_xor_sync(~0u, acc0, 8)) + b_obj[lane & 7];
    float v1 = 0.5f * (acc1 + __shfl_xor_sync(~0u, acc1, 8)) + b_ctx[lane & 7];
    float v2 = 0.5f * (acc2 + __shfl_xor_sync(~0u, acc2, 8)) + b_co[lane & 7];
    float mv0 = v0, mv1 = v1, mv2 = v2;
    for (int o = 4; o; o >>= 1) {
        mv0 = fmaxf(mv0, __shfl_xor_sync(~0u, mv0, o, 8));
        mv1 = fmaxf(mv1, __shfl_xor_sync(~0u, mv1, o, 8));
        mv2 = fmaxf(mv2, __shfl_xor_sync(~0u, mv2, o, 8));
    }
    float se0 = __expf(v0 - mv0), se1 = __expf(v1 - mv1), se2 = __expf(v2 - mv2);
    for (int o = 4; o; o >>= 1) {
        se0 += __shfl_xor_sync(~0u, se0, o, 8);
        se1 += __shfl_xor_sync(~0u, se1, o, 8);
        se2 += __shfl_xor_sync(~0u, se2, o, 8);
    }
    if (lane < 8) {
        stcs1(out + O0 + (size_t)n * 8 + lane, v0 - mv0 - __logf(se0));
        stcs1(out + O1 + (size_t)n * 8 + lane, v1 - mv1 - __logf(se1));
        stcs1(out + O2 + (size_t)n * 8 + lane, v2 - mv2 - __logf(se2));
    }
}

// ------------------- launch -------------------
extern "C" void kernel_launch(void* const* d_in, const int* in_sizes, int n_in,
                              void* d_out, int out_size) {
    const float* x      = (const float*)d_in[0];
    const int*   ei     = (const int*)d_in[1];
    const float* W_feat = (const float*)d_in[2];
    const float* a_s_f  = (const float*)d_in[3];
    const float* a_d_f  = (const float*)d_in[4];
    const float* b_feat = (const float*)d_in[5];
    const float* W_mlp  = (const float*)d_in[6];
    const float* b_mlp  = (const float*)d_in[7];
    const float* W_obj  = (const float*)d_in[8];
    const float* a_s_o  = (const float*)d_in[9];
    const float* a_d_o  = (const float*)d_in[10];
    const float* b_obj  = (const float*)d_in[11];
    const float* W_ctx  = (const float*)d_in[12];
    const float* a_s_c  = (const float*)d_in[13];
    const float* a_d_c  = (const float*)d_in[14];
    const float* b_ctx  = (const float*)d_in[15];
    const float* W_co   = (const float*)d_in[16];
    const float* a_s_x  = (const float*)d_in[17];
    const float* a_d_x  = (const float*)d_in[18];
    const float* b_co   = (const float*)d_in[19];
    float* out = (float*)d_out;

    const int GEMM1_SMEM = 128 * 128 * 4 + 2 * 8 * 256 * 4;   // 81920 B
    cudaFuncSetAttribute(k_gemm1, cudaFuncAttributeMaxDynamicSharedMemorySize, GEMM1_SMEM);

    // order: conv1 is the 4th launch (ncu capture slot)
    k_gemm1<<<NB1, 512, GEMM1_SMEM>>>(x, W_feat, a_s_f, a_d_f, ei);   // fused hist
    k_scan<<<1, 1024>>>();
    k_scatter<<<(EE / 2 + NN + 255) / 256, 256>>>(ei);
    k_conv1<<<(NN + 3) / 4, 128>>>(b_feat, W_mlp, b_mlp, out);

    k_gemm2<<<NN / 16, 256>>>(W_obj, W_ctx, W_co,
                              a_s_o, a_d_o, a_s_c, a_d_c, a_s_x, a_d_x);
    k_conv2m<<<(NN + 3) / 4, 128>>>(b_obj, b_ctx, b_co, out);
}

// round 15
// speedup vs baseline: 1.2374x; 1.1695x over previous
#include <cuda_runtime.h>
#include <cstdint>

#define NN 50000
#define EE 800000
#define ET (EE + NN)
#define NB1 391                       // gemm1 blocks: ceil(50000/128)
#define NB2 391                       // gemm2 blocks: ceil(50000/128)

// output layout: xo_logis [N,8] | xc_logis [N,8] | xco_logis [N,8] | elu(xo) [N,256] | elu(xc) [N,256]
#define O0 0
#define O1 (NN*8)
#define O2 (2*NN*8)
#define O3 (3*NN*8)
#define O4 (3*NN*8 + NN*256)

typedef unsigned long long ull;

__device__ __forceinline__ ull pk2(float lo, float hi) {
    ull r; asm("mov.b64 %0, {%1, %2};" : "=l"(r) : "f"(lo), "f"(hi)); return r;
}
__device__ __forceinline__ void upk2(ull v, float& lo, float& hi) {
    asm("mov.b64 {%0, %1}, %2;" : "=f"(lo), "=f"(hi) : "l"(v));
}
#define FMA2(d, a, b) asm("fma.rn.f32x2 %0, %1, %2, %0;" : "+l"(d) : "l"(a), "l"(b))

__device__ __forceinline__ void stcs4(float* p, float4 v) {
    asm volatile("st.global.cs.v4.f32 [%0], {%1,%2,%3,%4};" :: "l"(p),
                 "f"(v.x), "f"(v.y), "f"(v.z), "f"(v.w) : "memory");
}
__device__ __forceinline__ void stcs1(float* p, float v) {
    asm volatile("st.global.cs.f32 [%0], %1;" :: "l"(p), "f"(v) : "memory");
}

// ------------------- static scratch (zero-initialized at module load) -------------------
__device__ int   g_deg[NN];          // ALWAYS zero at kernel_launch entry (scan re-zeroes)
__device__ int   g_rowptr[NN + 1];
__device__ int   g_wptr[NN];
__device__ int   g_srt[ET];

__device__ __align__(16) float  g_hfeat[(size_t)NN * 256];
__device__ __align__(16) float  g_h1[(size_t)NN * 256];
__device__ __align__(16) float2 g_att[NN];

__device__ __align__(16) float g_als[NN * 4], g_ald[NN * 4];
__device__ __align__(16) float g_gall[(size_t)NN * 48];
__device__ __align__(16) float g_alsP[NN * 8], g_aldP[NN * 8];

__device__ __forceinline__ float lrelu(float v) { return v > 0.f ? v : 0.2f * v; }
// fast ELU: MUFU-based exp instead of the ~20-instr expm1f software sequence
__device__ __forceinline__ float eluf(float v)  { return v > 0.f ? v : __expf(v) - 1.f; }

// ------------------- CSR scan + scatter -------------------
__global__ void k_scan() {
    __shared__ int sums[1024];
    int tid = threadIdx.x;
    const int chunk = (NN + 1023) / 1024;
    int start = tid * chunk;
    int s = 0;
    for (int i = 0; i < chunk; i++) {
        int idx = start + i;
        if (idx < NN) s += g_deg[idx] + 1;   // +1 = self loop
    }
    sums[tid] = s;
    __syncthreads();
    for (int off = 1; off < 1024; off <<= 1) {
        int v = 0;
        if (tid >= off) v = sums[tid - off];
        __syncthreads();
        if (tid >= off) sums[tid] += v;
        __syncthreads();
    }
    int prefix = (tid == 0) ? 0 : sums[tid - 1];
    for (int i = 0; i < chunk; i++) {
        int idx = start + i;
        if (idx < NN) {
            g_rowptr[idx] = prefix;
            g_wptr[idx] = prefix;
            prefix += g_deg[idx] + 1;
            g_deg[idx] = 0;                  // restore invariant for next call
        }
    }
    if (tid == 0) g_rowptr[NN] = sums[1023];
}

__global__ void k_scatter(const int* __restrict__ ei) {
    int i = blockIdx.x * blockDim.x + threadIdx.x;
    if (i < EE / 2) {
        int2 s2 = ((const int2*)ei)[i];
        int2 d2 = ((const int2*)(ei + EE))[i];
        int p0 = atomicAdd(&g_wptr[d2.x], 1);
        g_srt[p0] = s2.x;
        int p1 = atomicAdd(&g_wptr[d2.y], 1);
        g_srt[p1] = s2.y;
    } else if (i < EE / 2 + NN) {
        int n = i - EE / 2;
        int pos = atomicAdd(&g_wptr[n], 1);
        g_srt[pos] = n;                      // self loop
    }
}

// ------------------- GEMM1: 128x256 tile, 512 thr, thread = 8 rows x (4+4 cols), fused hist -------------------
__global__ __launch_bounds__(512) void k_gemm1(
    const float* __restrict__ x, const float* __restrict__ Wf,
    const float* __restrict__ a_s, const float* __restrict__ a_d,
    const int* __restrict__ ei) {
    extern __shared__ float smem[];
    float (*xs)[128] = (float (*)[128])smem;                        // 128 x 128 = 64 KB
    float (*Bs)[8][256] = (float (*)[8][256])(smem + 128 * 128);    // [2][8][256] = 16 KB
    int tid = threadIdx.x;
    int n0 = blockIdx.x * 128;
    int ty = tid >> 5, tx = tid & 31;       // ty 0..15 -> 8-row group

    // fused edge histogram (independent of GEMM data flow)
    for (int i = blockIdx.x * 512 + tid; i < EE / 2; i += NB1 * 512) {
        int2 d = ((const int2*)(ei + EE))[i];
        atomicAdd(&g_deg[d.x], 1);
        atomicAdd(&g_deg[d.y], 1);
    }

    // fill xs: 4096 float4, 8 per thread
#pragma unroll
    for (int i = 0; i < 8; i++) {
        int idx4 = tid + i * 512;
        int row = idx4 >> 5, kq = idx4 & 31;
        float4 v = make_float4(0, 0, 0, 0);
        if (n0 + row < NN) v = *(const float4*)(x + (size_t)(n0 + row) * 128 + kq * 4);
        *(float4*)&xs[row][kq * 4] = v;
    }

    // prefetch kt=0 W slab
    int pkk = tid >> 6, pcc = (tid & 63) * 4;
    float4 pre = *(const float4*)(Wf + (size_t)pkk * 256 + pcc);
    *(float4*)&Bs[0][pkk][pcc] = pre;

    float4 asA = *(const float4*)(a_s + tx * 4);
    float4 asB = *(const float4*)(a_s + 128 + tx * 4);
    float4 adA = *(const float4*)(a_d + tx * 4);
    float4 adB = *(const float4*)(a_d + 128 + tx * 4);

    ull accp[8][4];
#pragma unroll
    for (int i = 0; i < 8; i++)
#pragma unroll
        for (int j = 0; j < 4; j++) accp[i][j] = 0ull;

    __syncthreads();

    for (int kt = 0; kt < 16; kt++) {
        if (kt < 15)
            pre = *(const float4*)(Wf + (size_t)((kt + 1) * 8 + pkk) * 256 + pcc);
        const float (*B)[256] = Bs[kt & 1];
#pragma unroll
        for (int half = 0; half < 2; half++) {
            {
                ull b[4][2];
#pragma unroll
                for (int kk = 0; kk < 4; kk++) {
                    float4 t = *(const float4*)&B[half * 4 + kk][tx * 4];
                    b[kk][0] = pk2(t.x, t.y); b[kk][1] = pk2(t.z, t.w);
                }
#pragma unroll
                for (int i = 0; i < 8; i++) {
                    float4 af = *(const float4*)&xs[ty * 8 + i][kt * 8 + half * 4];
                    ull a0 = pk2(af.x, af.x), a1 = pk2(af.y, af.y);
                    ull a2 = pk2(af.z, af.z), a3 = pk2(af.w, af.w);
                    FMA2(accp[i][0], a0, b[0][0]); FMA2(accp[i][1], a0, b[0][1]);
                    FMA2(accp[i][0], a1, b[1][0]); FMA2(accp[i][1], a1, b[1][1]);
                    FMA2(accp[i][0], a2, b[2][0]); FMA2(accp[i][1], a2, b[2][1]);
                    FMA2(accp[i][0], a3, b[3][0]); FMA2(accp[i][1], a3, b[3][1]);
                }
            }
            {
                ull b[4][2];
#pragma unroll
                for (int kk = 0; kk < 4; kk++) {
                    float4 t = *(const float4*)&B[half * 4 + kk][128 + tx * 4];
                    b[kk][0] = pk2(t.x, t.y); b[kk][1] = pk2(t.z, t.w);
                }
#pragma unroll
                for (int i = 0; i < 8; i++) {
                    float4 af = *(const float4*)&xs[ty * 8 + i][kt * 8 + half * 4];
                    ull a0 = pk2(af.x, af.x), a1 = pk2(af.y, af.y);
                    ull a2 = pk2(af.z, af.z), a3 = pk2(af.w, af.w);
                    FMA2(accp[i][2], a0, b[0][0]); FMA2(accp[i][3], a0, b[0][1]);
                    FMA2(accp[i][2], a1, b[1][0]); FMA2(accp[i][3], a1, b[1][1]);
                    FMA2(accp[i][2], a2, b[2][0]); FMA2(accp[i][3], a2, b[2][1]);
                    FMA2(accp[i][2], a3, b[3][0]); FMA2(accp[i][3], a3, b[3][1]);
                }
            }
        }
        if (kt < 15) {
            *(float4*)&Bs[(kt + 1) & 1][pkk][pcc] = pre;
            __syncthreads();
        }
    }

    // epilogue: store hfeat + fused attention-logit dots
#pragma unroll
    for (int i = 0; i < 8; i++) {
        int row = n0 + ty * 8 + i;
        bool ok = row < NN;
        float4 vA, vB;
        upk2(accp[i][0], vA.x, vA.y); upk2(accp[i][1], vA.z, vA.w);
        upk2(accp[i][2], vB.x, vB.y); upk2(accp[i][3], vB.z, vB.w);
        if (ok) {
            *(float4*)(g_hfeat + (size_t)row * 256 + tx * 4)       = vA;
            *(float4*)(g_hfeat + (size_t)row * 256 + 128 + tx * 4) = vB;
        }
        float psA = vA.x * asA.x + vA.y * asA.y + vA.z * asA.z + vA.w * asA.w;
        float psB = vB.x * asB.x + vB.y * asB.y + vB.z * asB.z + vB.w * asB.w;
        float pdA = vA.x * adA.x + vA.y * adA.y + vA.z * adA.z + vA.w * adA.w;
        float pdB = vB.x * adB.x + vB.y * adB.y + vB.z * adB.z + vB.w * adB.w;
        for (int o = 1; o < 16; o <<= 1) {
            psA += __shfl_xor_sync(~0u, psA, o);
            psB += __shfl_xor_sync(~0u, psB, o);
            pdA += __shfl_xor_sync(~0u, pdA, o);
            pdB += __shfl_xor_sync(~0u, pdB, o);
        }
        if ((tx & 15) == 0 && ok) {
            int hA = tx >> 4;
            g_als[row * 4 + hA]     = psA;
            g_als[row * 4 + 2 + hA] = psB;
            g_ald[row * 4 + hA]     = pdA;
            g_ald[row * 4 + 2 + hA] = pdB;
        }
    }
}

// ------------------- big conv: warp per dst node, single pass, unrolled LDG.128 gather -------------------
__global__ __launch_bounds__(128) void k_conv1(
    const float* __restrict__ b_feat, const float* __restrict__ W_mlp,
    const float* __restrict__ b_mlp, float* __restrict__ out) {
    __shared__ int    ss[4][32];
    __shared__ float4 sp[4][32];
    int w = threadIdx.x >> 5;
    int gwarp = (blockIdx.x * blockDim.x + threadIdx.x) >> 5;
    int lane = threadIdx.x & 31;
    if (gwarp >= NN) return;
    int n = gwarp;
    int beg = g_rowptr[n], end = g_rowptr[n + 1];

    const float4* als4 = (const float4*)g_als;
    float4 ad = ((const float4*)g_ald)[n];
    bool lo16 = lane < 16;

    float s0 = 0.f, s1 = 0.f, s2 = 0.f, s3 = 0.f;
    ull acc0 = 0, acc1 = 0, acc2 = 0, acc3 = 0;

    for (int base = beg; base < end; base += 32) {
        int idx = base + lane;
        int sl = 0;
        float4 pv = make_float4(0, 0, 0, 0);
        if (idx < end) {
            sl = g_srt[idx];
            float4 as = als4[sl];
            pv.x = __expf(lrelu(as.x + ad.x));
            pv.y = __expf(lrelu(as.y + ad.y));
            pv.z = __expf(lrelu(as.z + ad.z));
            pv.w = __expf(lrelu(as.w + ad.w));
            s0 += pv.x; s1 += pv.y; s2 += pv.z; s3 += pv.w;
        }
        __syncwarp();
        ss[w][lane] = sl;
        sp[w][lane] = pv;
        __syncwarp();
        int cnt = min(32, end - base);
        int j = 0;
#pragma unroll 1
        for (; j + 2 <= cnt; j += 2) {
            int sb0 = ss[w][j], sb1 = ss[w][j + 1];
            float4 pj0 = sp[w][j], pj1 = sp[w][j + 1];
            const float4* hr0 = (const float4*)(g_hfeat + (size_t)sb0 * 256);
            const float4* hr1 = (const float4*)(g_hfeat + (size_t)sb1 * 256);
            float4 hA0 = hr0[lane], hB0 = hr0[lane + 32];
            float4 hA1 = hr1[lane], hB1 = hr1[lane + 32];
            float aA0 = lo16 ? pj0.x : pj0.y, aB0 = lo16 ? pj0.z : pj0.w;
            float aA1 = lo16 ? pj1.x : pj1.y, aB1 = lo16 ? pj1.z : pj1.w;
            ull aA0p = pk2(aA0, aA0), aB0p = pk2(aB0, aB0);
            ull aA1p = pk2(aA1, aA1), aB1p = pk2(aB1, aB1);
            FMA2(acc0, aA0p, pk2(hA0.x, hA0.y));
            FMA2(acc1, aA0p, pk2(hA0.z, hA0.w));
            FMA2(acc2, aB0p, pk2(hB0.x, hB0.y));
            FMA2(acc3, aB0p, pk2(hB0.z, hB0.w));
            FMA2(acc0, aA1p, pk2(hA1.x, hA1.y));
            FMA2(acc1, aA1p, pk2(hA1.z, hA1.w));
            FMA2(acc2, aB1p, pk2(hB1.x, hB1.y));
            FMA2(acc3, aB1p, pk2(hB1.z, hB1.w));
        }
        if (j < cnt) {
            int sb = ss[w][j];
            float4 pj = sp[w][j];
            const float4* hr4 = (const float4*)(g_hfeat + (size_t)sb * 256);
            float4 hA = hr4[lane], hB = hr4[lane + 32];
            float aA = lo16 ? pj.x : pj.y, aB = lo16 ? pj.z : pj.w;
            ull aAp = pk2(aA, aA), aBp = pk2(aB, aB);
            FMA2(acc0, aAp, pk2(hA.x, hA.y));
            FMA2(acc1, aAp, pk2(hA.z, hA.w));
            FMA2(acc2, aBp, pk2(hB.x, hB.y));
            FMA2(acc3, aBp, pk2(hB.z, hB.w));
        }
    }

    for (int o = 16; o; o >>= 1) {
        s0 += __shfl_xor_sync(~0u, s0, o);
        s1 += __shfl_xor_sync(~0u, s1, o);
        s2 += __shfl_xor_sync(~0u, s2, o);
        s3 += __shfl_xor_sync(~0u, s3, o);
    }
    float i0 = 1.f / (s0 + 1e-16f), i1 = 1.f / (s1 + 1e-16f);
    float i2 = 1.f / (s2 + 1e-16f), i3 = 1.f / (s3 + 1e-16f);
    float invA = lo16 ? i0 : i1;
    float invB = lo16 ? i2 : i3;

    float a0, a1, a2, a3, b0, b1, b2, b3;
    upk2(acc0, a0, a1); upk2(acc1, a2, a3);
    upk2(acc2, b0, b1); upk2(acc3, b2, b3);
    float4 bfA = *(const float4*)(b_feat + 4 * lane);
    float4 bfB = *(const float4*)(b_feat + 128 + 4 * lane);
    float heA0 = eluf(a0 * invA + bfA.x), heA1 = eluf(a1 * invA + bfA.y);
    float heA2 = eluf(a2 * invA + bfA.z), heA3 = eluf(a3 * invA + bfA.w);
    float heB0 = eluf(b0 * invB + bfB.x), heB1 = eluf(b1 * invB + bfB.y);
    float heB2 = eluf(b2 * invB + bfB.z), heB3 = eluf(b3 * invB + bfB.w);
    *(float4*)(g_h1 + (size_t)n * 256 + 4 * lane)       = make_float4(heA0, heA1, heA2, heA3);
    *(float4*)(g_h1 + (size_t)n * 256 + 128 + 4 * lane) = make_float4(heB0, heB1, heB2, heB3);

    float4 wA0 = *(const float4*)(W_mlp + 8 * lane);
    float4 wA1 = *(const float4*)(W_mlp + 8 * lane + 4);
    float4 wB0 = *(const float4*)(W_mlp + 256 + 8 * lane);
    float4 wB1 = *(const float4*)(W_mlp + 256 + 8 * lane + 4);
    float l0 = heA0 * wA0.x + heA1 * wA0.z + heA2 * wA1.x + heA3 * wA1.z
             + heB0 * wB0.x + heB1 * wB0.z + heB2 * wB1.x + heB3 * wB1.z;
    float l1 = heA0 * wA0.y + heA1 * wA0.w + heA2 * wA1.y + heA3 * wA1.w
             + heB0 * wB0.y + heB1 * wB0.w + heB2 * wB1.y + heB3 * wB1.w;
    for (int o = 16; o; o >>= 1) {
        l0 += __shfl_xor_sync(~0u, l0, o);
        l1 += __shfl_xor_sync(~0u, l1, o);
    }
    l0 += b_mlp[0];
    l1 += b_mlp[1];
    float mm = fmaxf(l0, l1);
    float e0 = __expf(l0 - mm), e1 = __expf(l1 - mm);
    float inv2 = 1.f / (e0 + e1);
    float att0 = e0 * inv2, att1 = e1 * inv2;
    if (lane == 0) g_att[n] = make_float2(att0, att1);

    stcs4(out + O3 + (size_t)n * 256 + 4 * lane,
          make_float4(eluf(att0 * heA0), eluf(att0 * heA1), eluf(att0 * heA2), eluf(att0 * heA3)));
    stcs4(out + O3 + (size_t)n * 256 + 128 + 4 * lane,
          make_float4(eluf(att0 * heB0), eluf(att0 * heB1), eluf(att0 * heB2), eluf(att0 * heB3)));
    stcs4(out + O4 + (size_t)n * 256 + 4 * lane,
          make_float4(eluf(att1 * heA0), eluf(att1 * heA1), eluf(att1 * heA2), eluf(att1 * heA3)));
    stcs4(out + O4 + (size_t)n * 256 + 128 + 4 * lane,
          make_float4(eluf(att1 * heB0), eluf(att1 * heB1), eluf(att1 * heB2), eluf(att1 * heB3)));
}

// ------------------- GEMM2 (register-tiled): Y[N,48] = h1 @ [Wo|Wc|Wx], att-scaled, + al dots -------------------
// 128 nodes/block, 256 threads = 16 ty x 16 tx; thread = 8 rows x 3 cols (tx, 16+tx, 32+tx)
// smem: A [128][68] floats (34816 B) then Wt [48][66] (12672 B); ysm [128][50] reuses A region.
#define G2_ASTRIDE 68
#define G2_WSTRIDE 66
#define G2_YSTRIDE 50
#define G2_SMEM (128 * G2_ASTRIDE * 4 + 48 * G2_WSTRIDE * 4)

__global__ __launch_bounds__(256) void k_gemm2(
    const float* __restrict__ Wo, const float* __restrict__ Wc, const float* __restrict__ Wx,
    const float* __restrict__ aso, const float* __restrict__ ado,
    const float* __restrict__ asc, const float* __restrict__ adc,
    const float* __restrict__ asx, const float* __restrict__ adx) {
    extern __shared__ float smem[];
    float* As = smem;                          // [128][68]
    float* Wt = smem + 128 * G2_ASTRIDE;       // [48][66], k-contiguous
    float* ysm = smem;                         // [128][50], reuses A after compute

    int tid = threadIdx.x;
    int n0 = blockIdx.x * 128;
    int ty = tid >> 4, tx = tid & 15;

    ull acc[8][3];
#pragma unroll
    for (int i = 0; i < 8; i++)
#pragma unroll
        for (int v = 0; v < 3; v++) acc[i][v] = 0ull;

    for (int ch = 0; ch < 4; ch++) {           // K chunks of 64
        __syncthreads();
        // fill A: 128 rows x 64 k = 2048 float4, 8 per thread
#pragma unroll
        for (int i = 0; i < 8; i++) {
            int idx4 = tid + i * 256;
            int row = idx4 >> 4, q = idx4 & 15;
            float4 v = make_float4(0, 0, 0, 0);
            if (n0 + row < NN)
                v = *(const float4*)(g_h1 + (size_t)(n0 + row) * 256 + ch * 64 + q * 4);
            *(float4*)&As[row * G2_ASTRIDE + q * 4] = v;
        }
        // fill Wt: 48 cols x 64 k = 3072, 12 per thread
#pragma unroll
        for (int i = 0; i < 12; i++) {
            int idx = tid + i * 256;
            int ca = idx >> 6, kk = idx & 63;
            int v = ca >> 4, c = ca & 15;
            const float* W = (v == 0) ? Wo : (v == 1) ? Wc : Wx;
            Wt[ca * G2_WSTRIDE + kk] = W[(size_t)(ch * 64 + kk) * 16 + c];
        }
        __syncthreads();
        // compute: 32 k-pairs
#pragma unroll 8
        for (int kp = 0; kp < 32; kp++) {
            ull w0 = *(const ull*)&Wt[tx * G2_WSTRIDE + kp * 2];
            ull w1 = *(const ull*)&Wt[(16 + tx) * G2_WSTRIDE + kp * 2];
            ull w2 = *(const ull*)&Wt[(32 + tx) * G2_WSTRIDE + kp * 2];
#pragma unroll
            for (int i = 0; i < 8; i++) {
                ull a = *(const ull*)&As[(ty * 8 + i) * G2_ASTRIDE + kp * 2];
                FMA2(acc[i][0], a, w0);
                FMA2(acc[i][1], a, w1);
                FMA2(acc[i][2], a, w2);
            }
        }
    }

    __syncthreads();   // done reading As; ysm may overwrite

    // epilogue: att-scale, store g_gall + ysm
#pragma unroll
    for (int i = 0; i < 8; i++) {
        int lrow = ty * 8 + i;
        int row = n0 + lrow;
        float lo, hi;
        upk2(acc[i][0], lo, hi); float y0 = lo + hi;
        upk2(acc[i][1], lo, hi); float y1 = lo + hi;
        upk2(acc[i][2], lo, hi); float y2 = lo + hi;
        if (row < NN) {
            float2 att = g_att[row];
            y0 *= att.x;
            y1 *= att.y;
            float* gr = g_gall + (size_t)row * 48;
            gr[tx] = y0; gr[16 + tx] = y1; gr[32 + tx] = y2;
        }
        ysm[lrow * G2_YSTRIDE + tx]      = y0;
        ysm[lrow * G2_YSTRIDE + 16 + tx] = y1;
        ysm[lrow * G2_YSTRIDE + 32 + tx] = y2;
    }
    __syncthreads();

    // al dots: 128 nodes x 12 = 1536 dots, 6 per thread
#pragma unroll
    for (int j = 0; j < 6; j++) {
        int d = tid * 6 + j;
        int nl = d / 12, r = d % 12;
        int v = r >> 2, h = (r >> 1) & 1, sd = r & 1;
        int row = n0 + nl;
        if (row >= NN) continue;
        const float* a = sd ? ((v == 0) ? ado : (v == 1) ? adc : adx)
                            : ((v == 0) ? aso : (v == 1) ? asc : asx);
        const float* yy = ysm + nl * G2_YSTRIDE + v * 16 + h * 8;
        float s = 0.f;
#pragma unroll
        for (int o = 0; o < 8; o++) s += yy[o] * a[h * 8 + o];
        float* dstp = sd ? g_aldP : g_alsP;
        dstp[row * 8 + v * 2 + h] = s;
    }
}

// ------------------- merged small convs: warp per dst node, single pass, unrolled -------------------
__global__ __launch_bounds__(128) void k_conv2m(
    const float* __restrict__ b_obj, const float* __restrict__ b_ctx,
    const float* __restrict__ b_co, float* __restrict__ out) {
    __shared__ int    ss[4][32];
    __shared__ float4 spA[4][32];
    __shared__ float2 spB[4][32];
    int w = threadIdx.x >> 5;
    int gwarp = (blockIdx.x * blockDim.x + threadIdx.x) >> 5;
    int lane = threadIdx.x & 31;
    if (gwarp >= NN) return;
    int n = gwarp;
    int beg = g_rowptr[n], end = g_rowptr[n + 1];

    float4 dA = *(const float4*)(g_aldP + n * 8);
    float2 dB = *(const float2*)(g_aldP + n * 8 + 4);
    float ald[6] = {dA.x, dA.y, dA.z, dA.w, dB.x, dB.y};

    int sub = lane & 15;
    int hh = (lane >> 3) & 1;
    float s[6] = {0, 0, 0, 0, 0, 0};
    float acc0 = 0.f, acc1 = 0.f, acc2 = 0.f;

    for (int base = beg; base < end; base += 32) {
        int idx = base + lane;
        int sl = 0;
        float p[6] = {0, 0, 0, 0, 0, 0};
        if (idx < end) {
            sl = g_srt[idx];
            float4 sA = *(const float4*)(g_alsP + sl * 8);
            float2 sB = *(const float2*)(g_alsP + sl * 8 + 4);
            float als[6] = {sA.x, sA.y, sA.z, sA.w, sB.x, sB.y};
#pragma unroll
            for (int k = 0; k < 6; k++) {
                p[k] = __expf(lrelu(als[k] + ald[k]));
                s[k] += p[k];
            }
        }
        __syncwarp();
        ss[w][lane] = sl;
        spA[w][lane] = make_float4(p[0], p[1], p[2], p[3]);
        spB[w][lane] = make_float2(p[4], p[5]);
        __syncwarp();
        int cnt = min(32, end - base);
        int j = 0;
#pragma unroll 1
        for (; j + 2 <= cnt; j += 2) {
            int sb0 = ss[w][j], sb1 = ss[w][j + 1];
            float4 qA0 = spA[w][j], qA1 = spA[w][j + 1];
            float2 qB0 = spB[w][j], qB1 = spB[w][j + 1];
            const float* g0 = g_gall + (size_t)sb0 * 48;
            const float* g1 = g_gall + (size_t)sb1 * 48;
            float x00 = g0[sub], x01 = g0[16 + sub], x02 = g0[32 + sub];
            float x10 = g1[sub], x11 = g1[16 + sub], x12 = g1[32 + sub];
            acc0 += (hh ? qA0.y : qA0.x) * x00 + (hh ? qA1.y : qA1.x) * x10;
            acc1 += (hh ? qA0.w : qA0.z) * x01 + (hh ? qA1.w : qA1.z) * x11;
            acc2 += (hh ? qB0.y : qB0.x) * x02 + (hh ? qB1.y : qB1.x) * x12;
        }
        if (j < cnt) {
            int sb = ss[w][j];
            float4 qA = spA[w][j];
            float2 qB = spB[w][j];
            const float* gr = g_gall + (size_t)sb * 48;
            acc0 += (hh ? qA.y : qA.x) * gr[sub];
            acc1 += (hh ? qA.w : qA.z) * gr[16 + sub];
            acc2 += (hh ? qB.y : qB.x) * gr[32 + sub];
        }
    }

    for (int o = 16; o; o >>= 1) {
#pragma unroll
        for (int k = 0; k < 6; k++) s[k] += __shfl_xor_sync(~0u, s[k], o);
    }
    acc0 *= 1.f / (s[hh] + 1e-16f);
    acc1 *= 1.f / (s[2 + hh] + 1e-16f);
    acc2 *= 1.f / (s[4 + hh] + 1e-16f);

    float v0 = 0.5f * (acc0 + __shfl_xor_sync(~0u, acc0, 8)) + b_obj[lane & 7];
    float v1 = 0.5f * (acc1 + __shfl_xor_sync(~0u, acc1, 8)) + b_ctx[lane & 7];
    float v2 = 0.5f * (acc2 + __shfl_xor_sync(~0u, acc2, 8)) + b_co[lane & 7];
    float mv0 = v0, mv1 = v1, mv2 = v2;
    for (int o = 4; o; o >>= 1) {
        mv0 = fmaxf(mv0, __shfl_xor_sync(~0u, mv0, o, 8));
        mv1 = fmaxf(mv1, __shfl_xor_sync(~0u, mv1, o, 8));
        mv2 = fmaxf(mv2, __shfl_xor_sync(~0u, mv2, o, 8));
    }
    float se0 = __expf(v0 - mv0), se1 = __expf(v1 - mv1), se2 = __expf(v2 - mv2);
    for (int o = 4; o; o >>= 1) {
        se0 += __shfl_xor_sync(~0u, se0, o, 8);
        se1 += __shfl_xor_sync(~0u, se1, o, 8);
        se2 += __shfl_xor_sync(~0u, se2, o, 8);
    }
    if (lane < 8) {
        stcs1(out + O0 + (size_t)n * 8 + lane, v0 - mv0 - __logf(se0));
        stcs1(out + O1 + (size_t)n * 8 + lane, v1 - mv1 - __logf(se1));
        stcs1(out + O2 + (size_t)n * 8 + lane, v2 - mv2 - __logf(se2));
    }
}

// ------------------- launch -------------------
extern "C" void kernel_launch(void* const* d_in, const int* in_sizes, int n_in,
                              void* d_out, int out_size) {
    const float* x      = (const float*)d_in[0];
    const int*   ei     = (const int*)d_in[1];
    const float* W_feat = (const float*)d_in[2];
    const float* a_s_f  = (const float*)d_in[3];
    const float* a_d_f  = (const float*)d_in[4];
    const float* b_feat = (const float*)d_in[5];
    const float* W_mlp  = (const float*)d_in[6];
    const float* b_mlp  = (const float*)d_in[7];
    const float* W_obj  = (const float*)d_in[8];
    const float* a_s_o  = (const float*)d_in[9];
    const float* a_d_o  = (const float*)d_in[10];
    const float* b_obj  = (const float*)d_in[11];
    const float* W_ctx  = (const float*)d_in[12];
    const float* a_s_c  = (const float*)d_in[13];
    const float* a_d_c  = (const float*)d_in[14];
    const float* b_ctx  = (const float*)d_in[15];
    const float* W_co   = (const float*)d_in[16];
    const float* a_s_x  = (const float*)d_in[17];
    const float* a_d_x  = (const float*)d_in[18];
    const float* b_co   = (const float*)d_in[19];
    float* out = (float*)d_out;

    const int GEMM1_SMEM = 128 * 128 * 4 + 2 * 8 * 256 * 4;   // 81920 B
    cudaFuncSetAttribute(k_gemm1, cudaFuncAttributeMaxDynamicSharedMemorySize, GEMM1_SMEM);
    cudaFuncSetAttribute(k_gemm2, cudaFuncAttributeMaxDynamicSharedMemorySize, G2_SMEM);

    // order: conv1 is the 4th launch (ncu capture slot)
    k_gemm1<<<NB1, 512, GEMM1_SMEM>>>(x, W_feat, a_s_f, a_d_f, ei);   // fused hist
    k_scan<<<1, 1024>>>();
    k_scatter<<<(EE / 2 + NN + 255) / 256, 256>>>(ei);
    k_conv1<<<(NN + 3) / 4, 128>>>(b_feat, W_mlp, b_mlp, out);

    k_gemm2<<<NB2, 256, G2_SMEM>>>(W_obj, W_ctx, W_co,
                                   a_s_o, a_d_o, a_s_c, a_d_c, a_s_x, a_d_x);
    k_conv2m<<<(NN + 3) / 4, 128>>>(b_obj, b_ctx, b_co, out);
}

// round 16
// speedup vs baseline: 1.3205x; 1.0672x over previous
#include <cuda_runtime.h>
#include <cuda_fp16.h>
#include <cstdint>

#define NN 50000
#define EE 800000
#define ET (EE + NN)
#define NB1 391                       // gemm1 blocks: ceil(50000/128)
#define NB2 391                       // gemm2 blocks: ceil(50000/128)

// output layout: xo_logis [N,8] | xc_logis [N,8] | xco_logis [N,8] | elu(xo) [N,256] | elu(xc) [N,256]
#define O0 0
#define O1 (NN*8)
#define O2 (2*NN*8)
#define O3 (3*NN*8)
#define O4 (3*NN*8 + NN*256)

typedef unsigned long long ull;

__device__ __forceinline__ ull pk2(float lo, float hi) {
    ull r; asm("mov.b64 %0, {%1, %2};" : "=l"(r) : "f"(lo), "f"(hi)); return r;
}
__device__ __forceinline__ void upk2(ull v, float& lo, float& hi) {
    asm("mov.b64 {%0, %1}, %2;" : "=f"(lo), "=f"(hi) : "l"(v));
}
#define FMA2(d, a, b) asm("fma.rn.f32x2 %0, %1, %2, %0;" : "+l"(d) : "l"(a), "l"(b))

__device__ __forceinline__ void stcs4(float* p, float4 v) {
    asm volatile("st.global.cs.v4.f32 [%0], {%1,%2,%3,%4};" :: "l"(p),
                 "f"(v.x), "f"(v.y), "f"(v.z), "f"(v.w) : "memory");
}
__device__ __forceinline__ void stcs1(float* p, float v) {
    asm volatile("st.global.cs.f32 [%0], %1;" :: "l"(p), "f"(v) : "memory");
}

__device__ __forceinline__ uint pack_h2(float a, float b) {
    __half2 h = __floats2half2_rn(a, b);
    return *(uint*)&h;
}
__device__ __forceinline__ float2 unpack_h2(uint u) {
    return __half22float2(*(__half2*)&u);
}

// ------------------- static scratch (zero-initialized at module load) -------------------
__device__ int   g_deg[NN];          // ALWAYS zero at kernel_launch entry (scan re-zeroes)
__device__ int   g_rowptr[NN + 1];
__device__ int   g_wptr[NN];
__device__ int   g_srt[ET];

__device__ __align__(16) __half g_hfeat[(size_t)NN * 256];   // fp16 node features (x @ W_feat)
__device__ __align__(16) __half g_h1[(size_t)NN * 256];      // fp16 post-ELU hidden
__device__ __align__(16) float2 g_att[NN];

__device__ __align__(16) float g_als[NN * 4], g_ald[NN * 4];
__device__ __align__(16) float g_gall[(size_t)NN * 48];
__device__ __align__(16) float g_alsP[NN * 8], g_aldP[NN * 8];

__device__ __forceinline__ float lrelu(float v) { return v > 0.f ? v : 0.2f * v; }
// fast ELU: MUFU-based exp instead of the ~20-instr expm1f software sequence
__device__ __forceinline__ float eluf(float v)  { return v > 0.f ? v : __expf(v) - 1.f; }

// ------------------- CSR scan + scatter -------------------
__global__ void k_scan() {
    __shared__ int sums[1024];
    int tid = threadIdx.x;
    const int chunk = (NN + 1023) / 1024;
    int start = tid * chunk;
    int s = 0;
    for (int i = 0; i < chunk; i++) {
        int idx = start + i;
        if (idx < NN) s += g_deg[idx] + 1;   // +1 = self loop
    }
    sums[tid] = s;
    __syncthreads();
    for (int off = 1; off < 1024; off <<= 1) {
        int v = 0;
        if (tid >= off) v = sums[tid - off];
        __syncthreads();
        if (tid >= off) sums[tid] += v;
        __syncthreads();
    }
    int prefix = (tid == 0) ? 0 : sums[tid - 1];
    for (int i = 0; i < chunk; i++) {
        int idx = start + i;
        if (idx < NN) {
            g_rowptr[idx] = prefix;
            g_wptr[idx] = prefix;
            prefix += g_deg[idx] + 1;
            g_deg[idx] = 0;                  // restore invariant for next call
        }
    }
    if (tid == 0) g_rowptr[NN] = sums[1023];
}

__global__ void k_scatter(const int* __restrict__ ei) {
    int i = blockIdx.x * blockDim.x + threadIdx.x;
    if (i < EE / 2) {
        int2 s2 = ((const int2*)ei)[i];
        int2 d2 = ((const int2*)(ei + EE))[i];
        int p0 = atomicAdd(&g_wptr[d2.x], 1);
        g_srt[p0] = s2.x;
        int p1 = atomicAdd(&g_wptr[d2.y], 1);
        g_srt[p1] = s2.y;
    } else if (i < EE / 2 + NN) {
        int n = i - EE / 2;
        int pos = atomicAdd(&g_wptr[n], 1);
        g_srt[pos] = n;                      // self loop
    }
}

// ------------------- GEMM1: 128x256 tile, 512 thr, thread = 8 rows x (4+4 cols), fused hist -------------------
__global__ __launch_bounds__(512) void k_gemm1(
    const float* __restrict__ x, const float* __restrict__ Wf,
    const float* __restrict__ a_s, const float* __restrict__ a_d,
    const int* __restrict__ ei) {
    extern __shared__ float smem[];
    float (*xs)[128] = (float (*)[128])smem;                        // 128 x 128 = 64 KB
    float (*Bs)[8][256] = (float (*)[8][256])(smem + 128 * 128);    // [2][8][256] = 16 KB
    int tid = threadIdx.x;
    int n0 = blockIdx.x * 128;
    int ty = tid >> 5, tx = tid & 31;       // ty 0..15 -> 8-row group

    // fused edge histogram (independent of GEMM data flow)
    for (int i = blockIdx.x * 512 + tid; i < EE / 2; i += NB1 * 512) {
        int2 d = ((const int2*)(ei + EE))[i];
        atomicAdd(&g_deg[d.x], 1);
        atomicAdd(&g_deg[d.y], 1);
    }

    // fill xs: 4096 float4, 8 per thread
#pragma unroll
    for (int i = 0; i < 8; i++) {
        int idx4 = tid + i * 512;
        int row = idx4 >> 5, kq = idx4 & 31;
        float4 v = make_float4(0, 0, 0, 0);
        if (n0 + row < NN) v = *(const float4*)(x + (size_t)(n0 + row) * 128 + kq * 4);
        *(float4*)&xs[row][kq * 4] = v;
    }

    // prefetch kt=0 W slab
    int pkk = tid >> 6, pcc = (tid & 63) * 4;
    float4 pre = *(const float4*)(Wf + (size_t)pkk * 256 + pcc);
    *(float4*)&Bs[0][pkk][pcc] = pre;

    float4 asA = *(const float4*)(a_s + tx * 4);
    float4 asB = *(const float4*)(a_s + 128 + tx * 4);
    float4 adA = *(const float4*)(a_d + tx * 4);
    float4 adB = *(const float4*)(a_d + 128 + tx * 4);

    ull accp[8][4];
#pragma unroll
    for (int i = 0; i < 8; i++)
#pragma unroll
        for (int j = 0; j < 4; j++) accp[i][j] = 0ull;

    __syncthreads();

    for (int kt = 0; kt < 16; kt++) {
        if (kt < 15)
            pre = *(const float4*)(Wf + (size_t)((kt + 1) * 8 + pkk) * 256 + pcc);
        const float (*B)[256] = Bs[kt & 1];
#pragma unroll
        for (int half = 0; half < 2; half++) {
            {
                ull b[4][2];
#pragma unroll
                for (int kk = 0; kk < 4; kk++) {
                    float4 t = *(const float4*)&B[half * 4 + kk][tx * 4];
                    b[kk][0] = pk2(t.x, t.y); b[kk][1] = pk2(t.z, t.w);
                }
#pragma unroll
                for (int i = 0; i < 8; i++) {
                    float4 af = *(const float4*)&xs[ty * 8 + i][kt * 8 + half * 4];
                    ull a0 = pk2(af.x, af.x), a1 = pk2(af.y, af.y);
                    ull a2 = pk2(af.z, af.z), a3 = pk2(af.w, af.w);
                    FMA2(accp[i][0], a0, b[0][0]); FMA2(accp[i][1], a0, b[0][1]);
                    FMA2(accp[i][0], a1, b[1][0]); FMA2(accp[i][1], a1, b[1][1]);
                    FMA2(accp[i][0], a2, b[2][0]); FMA2(accp[i][1], a2, b[2][1]);
                    FMA2(accp[i][0], a3, b[3][0]); FMA2(accp[i][1], a3, b[3][1]);
                }
            }
            {
                ull b[4][2];
#pragma unroll
                for (int kk = 0; kk < 4; kk++) {
                    float4 t = *(const float4*)&B[half * 4 + kk][128 + tx * 4];
                    b[kk][0] = pk2(t.x, t.y); b[kk][1] = pk2(t.z, t.w);
                }
#pragma unroll
                for (int i = 0; i < 8; i++) {
                    float4 af = *(const float4*)&xs[ty * 8 + i][kt * 8 + half * 4];
                    ull a0 = pk2(af.x, af.x), a1 = pk2(af.y, af.y);
                    ull a2 = pk2(af.z, af.z), a3 = pk2(af.w, af.w);
                    FMA2(accp[i][2], a0, b[0][0]); FMA2(accp[i][3], a0, b[0][1]);
                    FMA2(accp[i][2], a1, b[1][0]); FMA2(accp[i][3], a1, b[1][1]);
                    FMA2(accp[i][2], a2, b[2][0]); FMA2(accp[i][3], a2, b[2][1]);
                    FMA2(accp[i][2], a3, b[3][0]); FMA2(accp[i][3], a3, b[3][1]);
                }
            }
        }
        if (kt < 15) {
            *(float4*)&Bs[(kt + 1) & 1][pkk][pcc] = pre;
            __syncthreads();
        }
    }

    // epilogue: store hfeat (fp16) + fused attention-logit dots (fp32)
#pragma unroll
    for (int i = 0; i < 8; i++) {
        int row = n0 + ty * 8 + i;
        bool ok = row < NN;
        float4 vA, vB;
        upk2(accp[i][0], vA.x, vA.y); upk2(accp[i][1], vA.z, vA.w);
        upk2(accp[i][2], vB.x, vB.y); upk2(accp[i][3], vB.z, vB.w);
        if (ok) {
            uint2 uA, uB;
            uA.x = pack_h2(vA.x, vA.y); uA.y = pack_h2(vA.z, vA.w);
            uB.x = pack_h2(vB.x, vB.y); uB.y = pack_h2(vB.z, vB.w);
            *(uint2*)(g_hfeat + (size_t)row * 256 + tx * 4)       = uA;
            *(uint2*)(g_hfeat + (size_t)row * 256 + 128 + tx * 4) = uB;
        }
        float psA = vA.x * asA.x + vA.y * asA.y + vA.z * asA.z + vA.w * asA.w;
        float psB = vB.x * asB.x + vB.y * asB.y + vB.z * asB.z + vB.w * asB.w;
        float pdA = vA.x * adA.x + vA.y * adA.y + vA.z * adA.z + vA.w * adA.w;
        float pdB = vB.x * adB.x + vB.y * adB.y + vB.z * adB.z + vB.w * adB.w;
        for (int o = 1; o < 16; o <<= 1) {
            psA += __shfl_xor_sync(~0u, psA, o);
            psB += __shfl_xor_sync(~0u, psB, o);
            pdA += __shfl_xor_sync(~0u, pdA, o);
            pdB += __shfl_xor_sync(~0u, pdB, o);
        }
        if ((tx & 15) == 0 && ok) {
            int hA = tx >> 4;
            g_als[row * 4 + hA]     = psA;
            g_als[row * 4 + 2 + hA] = psB;
            g_ald[row * 4 + hA]     = pdA;
            g_ald[row * 4 + 2 + hA] = pdB;
        }
    }
}

// ------------------- big conv: warp per dst node, single pass, fp16 gather -------------------
__global__ __launch_bounds__(128) void k_conv1(
    const float* __restrict__ b_feat, const float* __restrict__ W_mlp,
    const float* __restrict__ b_mlp, float* __restrict__ out) {
    __shared__ int    ss[4][32];
    __shared__ float4 sp[4][32];
    int w = threadIdx.x >> 5;
    int gwarp = (blockIdx.x * blockDim.x + threadIdx.x) >> 5;
    int lane = threadIdx.x & 31;
    if (gwarp >= NN) return;
    int n = gwarp;
    int beg = g_rowptr[n], end = g_rowptr[n + 1];

    const float4* als4 = (const float4*)g_als;
    float4 ad = ((const float4*)g_ald)[n];
    bool lo16 = lane < 16;

    float s0 = 0.f, s1 = 0.f, s2 = 0.f, s3 = 0.f;
    ull acc0 = 0, acc1 = 0, acc2 = 0, acc3 = 0;

    for (int base = beg; base < end; base += 32) {
        int idx = base + lane;
        int sl = 0;
        float4 pv = make_float4(0, 0, 0, 0);
        if (idx < end) {
            sl = g_srt[idx];
            float4 as = als4[sl];
            pv.x = __expf(lrelu(as.x + ad.x));
            pv.y = __expf(lrelu(as.y + ad.y));
            pv.z = __expf(lrelu(as.z + ad.z));
            pv.w = __expf(lrelu(as.w + ad.w));
            s0 += pv.x; s1 += pv.y; s2 += pv.z; s3 += pv.w;
        }
        __syncwarp();
        ss[w][lane] = sl;
        sp[w][lane] = pv;
        __syncwarp();
        int cnt = min(32, end - base);
        int j = 0;
#pragma unroll 1
        for (; j + 2 <= cnt; j += 2) {
            int sb0 = ss[w][j], sb1 = ss[w][j + 1];
            float4 pj0 = sp[w][j], pj1 = sp[w][j + 1];
            const uint2* hr0 = (const uint2*)(g_hfeat + (size_t)sb0 * 256);
            const uint2* hr1 = (const uint2*)(g_hfeat + (size_t)sb1 * 256);
            uint2 hA0 = hr0[lane], hB0 = hr0[lane + 32];
            uint2 hA1 = hr1[lane], hB1 = hr1[lane + 32];
            float aA0 = lo16 ? pj0.x : pj0.y, aB0 = lo16 ? pj0.z : pj0.w;
            float aA1 = lo16 ? pj1.x : pj1.y, aB1 = lo16 ? pj1.z : pj1.w;
            ull aA0p = pk2(aA0, aA0), aB0p = pk2(aB0, aB0);
            ull aA1p = pk2(aA1, aA1), aB1p = pk2(aB1, aB1);
            float2 fA0a = unpack_h2(hA0.x), fA0b = unpack_h2(hA0.y);
            float2 fB0a = unpack_h2(hB0.x), fB0b = unpack_h2(hB0.y);
            float2 fA1a = unpack_h2(hA1.x), fA1b = unpack_h2(hA1.y);
            float2 fB1a = unpack_h2(hB1.x), fB1b = unpack_h2(hB1.y);
            FMA2(acc0, aA0p, pk2(fA0a.x, fA0a.y));
            FMA2(acc1, aA0p, pk2(fA0b.x, fA0b.y));
            FMA2(acc2, aB0p, pk2(fB0a.x, fB0a.y));
            FMA2(acc3, aB0p, pk2(fB0b.x, fB0b.y));
            FMA2(acc0, aA1p, pk2(fA1a.x, fA1a.y));
            FMA2(acc1, aA1p, pk2(fA1b.x, fA1b.y));
            FMA2(acc2, aB1p, pk2(fB1a.x, fB1a.y));
            FMA2(acc3, aB1p, pk2(fB1b.x, fB1b.y));
        }
        if (j < cnt) {
            int sb = ss[w][j];
            float4 pj = sp[w][j];
            const uint2* hr = (const uint2*)(g_hfeat + (size_t)sb * 256);
            uint2 hA = hr[lane], hB = hr[lane + 32];
            float aA = lo16 ? pj.x : pj.y, aB = lo16 ? pj.z : pj.w;
            ull aAp = pk2(aA, aA), aBp = pk2(aB, aB);
            float2 fAa = unpack_h2(hA.x), fAb = unpack_h2(hA.y);
            float2 fBa = unpack_h2(hB.x), fBb = unpack_h2(hB.y);
            FMA2(acc0, aAp, pk2(fAa.x, fAa.y));
            FMA2(acc1, aAp, pk2(fAb.x, fAb.y));
            FMA2(acc2, aBp, pk2(fBa.x, fBa.y));
            FMA2(acc3, aBp, pk2(fBb.x, fBb.y));
        }
    }

    for (int o = 16; o; o >>= 1) {
        s0 += __shfl_xor_sync(~0u, s0, o);
        s1 += __shfl_xor_sync(~0u, s1, o);
        s2 += __shfl_xor_sync(~0u, s2, o);
        s3 += __shfl_xor_sync(~0u, s3, o);
    }
    float i0 = 1.f / (s0 + 1e-16f), i1 = 1.f / (s1 + 1e-16f);
    float i2 = 1.f / (s2 + 1e-16f), i3 = 1.f / (s3 + 1e-16f);
    float invA = lo16 ? i0 : i1;
    float invB = lo16 ? i2 : i3;

    float a0, a1, a2, a3, b0, b1, b2, b3;
    upk2(acc0, a0, a1); upk2(acc1, a2, a3);
    upk2(acc2, b0, b1); upk2(acc3, b2, b3);
    float4 bfA = *(const float4*)(b_feat + 4 * lane);
    float4 bfB = *(const float4*)(b_feat + 128 + 4 * lane);
    float heA0 = eluf(a0 * invA + bfA.x), heA1 = eluf(a1 * invA + bfA.y);
    float heA2 = eluf(a2 * invA + bfA.z), heA3 = eluf(a3 * invA + bfA.w);
    float heB0 = eluf(b0 * invB + bfB.x), heB1 = eluf(b1 * invB + bfB.y);
    float heB2 = eluf(b2 * invB + bfB.z), heB3 = eluf(b3 * invB + bfB.w);
    {
        uint2 uA, uB;
        uA.x = pack_h2(heA0, heA1); uA.y = pack_h2(heA2, heA3);
        uB.x = pack_h2(heB0, heB1); uB.y = pack_h2(heB2, heB3);
        *(uint2*)(g_h1 + (size_t)n * 256 + 4 * lane)       = uA;
        *(uint2*)(g_h1 + (size_t)n * 256 + 128 + 4 * lane) = uB;
    }

    float4 wA0 = *(const float4*)(W_mlp + 8 * lane);
    float4 wA1 = *(const float4*)(W_mlp + 8 * lane + 4);
    float4 wB0 = *(const float4*)(W_mlp + 256 + 8 * lane);
    float4 wB1 = *(const float4*)(W_mlp + 256 + 8 * lane + 4);
    float l0 = heA0 * wA0.x + heA1 * wA0.z + heA2 * wA1.x + heA3 * wA1.z
             + heB0 * wB0.x + heB1 * wB0.z + heB2 * wB1.x + heB3 * wB1.z;
    float l1 = heA0 * wA0.y + heA1 * wA0.w + heA2 * wA1.y + heA3 * wA1.w
             + heB0 * wB0.y + heB1 * wB0.w + heB2 * wB1.y + heB3 * wB1.w;
    for (int o = 16; o; o >>= 1) {
        l0 += __shfl_xor_sync(~0u, l0, o);
        l1 += __shfl_xor_sync(~0u, l1, o);
    }
    l0 += b_mlp[0];
    l1 += b_mlp[1];
    float mm = fmaxf(l0, l1);
    float e0 = __expf(l0 - mm), e1 = __expf(l1 - mm);
    float inv2 = 1.f / (e0 + e1);
    float att0 = e0 * inv2, att1 = e1 * inv2;
    if (lane == 0) g_att[n] = make_float2(att0, att1);

    stcs4(out + O3 + (size_t)n * 256 + 4 * lane,
          make_float4(eluf(att0 * heA0), eluf(att0 * heA1), eluf(att0 * heA2), eluf(att0 * heA3)));
    stcs4(out + O3 + (size_t)n * 256 + 128 + 4 * lane,
          make_float4(eluf(att0 * heB0), eluf(att0 * heB1), eluf(att0 * heB2), eluf(att0 * heB3)));
    stcs4(out + O4 + (size_t)n * 256 + 4 * lane,
          make_float4(eluf(att1 * heA0), eluf(att1 * heA1), eluf(att1 * heA2), eluf(att1 * heA3)));
    stcs4(out + O4 + (size_t)n * 256 + 128 + 4 * lane,
          make_float4(eluf(att1 * heB0), eluf(att1 * heB1), eluf(att1 * heB2), eluf(att1 * heB3)));
}

// ------------------- GEMM2 (register-tiled): Y[N,48] = h1 @ [Wo|Wc|Wx], att-scaled, + al dots -------------------
#define G2_ASTRIDE 68
#define G2_WSTRIDE 66
#define G2_YSTRIDE 50
#define G2_SMEM (128 * G2_ASTRIDE * 4 + 48 * G2_WSTRIDE * 4)

__global__ __launch_bounds__(256) void k_gemm2(
    const float* __restrict__ Wo, const float* __restrict__ Wc, const float* __restrict__ Wx,
    const float* __restrict__ aso, const float* __restrict__ ado,
    const float* __restrict__ asc, const float* __restrict__ adc,
    const float* __restrict__ asx, const float* __restrict__ adx) {
    extern __shared__ float smem[];
    float* As = smem;                          // [128][68]
    float* Wt = smem + 128 * G2_ASTRIDE;       // [48][66], k-contiguous
    float* ysm = smem;                         // [128][50], reuses A after compute

    int tid = threadIdx.x;
    int n0 = blockIdx.x * 128;
    int ty = tid >> 4, tx = tid & 15;

    ull acc[8][3];
#pragma unroll
    for (int i = 0; i < 8; i++)
#pragma unroll
        for (int v = 0; v < 3; v++) acc[i][v] = 0ull;

    for (int ch = 0; ch < 4; ch++) {           // K chunks of 64
        __syncthreads();
        // fill A: 128 rows x 64 k; load fp16, convert to fp32 in smem
#pragma unroll
        for (int i = 0; i < 8; i++) {
            int idx4 = tid + i * 256;
            int row = idx4 >> 4, q = idx4 & 15;
            float4 v = make_float4(0, 0, 0, 0);
            if (n0 + row < NN) {
                uint2 u = *(const uint2*)(g_h1 + (size_t)(n0 + row) * 256 + ch * 64 + q * 4);
                float2 f01 = unpack_h2(u.x), f23 = unpack_h2(u.y);
                v = make_float4(f01.x, f01.y, f23.x, f23.y);
            }
            *(float4*)&As[row * G2_ASTRIDE + q * 4] = v;
        }
        // fill Wt: 48 cols x 64 k = 3072, 12 per thread
#pragma unroll
        for (int i = 0; i < 12; i++) {
            int idx = tid + i * 256;
            int ca = idx >> 6, kk = idx & 63;
            int v = ca >> 4, c = ca & 15;
            const float* W = (v == 0) ? Wo : (v == 1) ? Wc : Wx;
            Wt[ca * G2_WSTRIDE + kk] = W[(size_t)(ch * 64 + kk) * 16 + c];
        }
        __syncthreads();
#pragma unroll 8
        for (int kp = 0; kp < 32; kp++) {
            ull w0 = *(const ull*)&Wt[tx * G2_WSTRIDE + kp * 2];
            ull w1 = *(const ull*)&Wt[(16 + tx) * G2_WSTRIDE + kp * 2];
            ull w2 = *(const ull*)&Wt[(32 + tx) * G2_WSTRIDE + kp * 2];
#pragma unroll
            for (int i = 0; i < 8; i++) {
                ull a = *(const ull*)&As[(ty * 8 + i) * G2_ASTRIDE + kp * 2];
                FMA2(acc[i][0], a, w0);
                FMA2(acc[i][1], a, w1);
                FMA2(acc[i][2], a, w2);
            }
        }
    }

    __syncthreads();   // done reading As; ysm may overwrite

#pragma unroll
    for (int i = 0; i < 8; i++) {
        int lrow = ty * 8 + i;
        int row = n0 + lrow;
        float lo, hi;
        upk2(acc[i][0], lo, hi); float y0 = lo + hi;
        upk2(acc[i][1], lo, hi); float y1 = lo + hi;
        upk2(acc[i][2], lo, hi); float y2 = lo + hi;
        if (row < NN) {
            float2 att = g_att[row];
            y0 *= att.x;
            y1 *= att.y;
            float* gr = g_gall + (size_t)row * 48;
            gr[tx] = y0; gr[16 + tx] = y1; gr[32 + tx] = y2;
        }
        ysm[lrow * G2_YSTRIDE + tx]      = y0;
        ysm[lrow * G2_YSTRIDE + 16 + tx] = y1;
        ysm[lrow * G2_YSTRIDE + 32 + tx] = y2;
    }
    __syncthreads();

#pragma unroll
    for (int j = 0; j < 6; j++) {
        int d = tid * 6 + j;
        int nl = d / 12, r = d % 12;
        int v = r >> 2, h = (r >> 1) & 1, sd = r & 1;
        int row = n0 + nl;
        if (row >= NN) continue;
        const float* a = sd ? ((v == 0) ? ado : (v == 1) ? adc : adx)
                            : ((v == 0) ? aso : (v == 1) ? asc : asx);
        const float* yy = ysm + nl * G2_YSTRIDE + v * 16 + h * 8;
        float s = 0.f;
#pragma unroll
        for (int o = 0; o < 8; o++) s += yy[o] * a[h * 8 + o];
        float* dstp = sd ? g_aldP : g_alsP;
        dstp[row * 8 + v * 2 + h] = s;
    }
}

// ------------------- merged small convs: warp per dst node, single pass, unrolled -------------------
__global__ __launch_bounds__(128) void k_conv2m(
    const float* __restrict__ b_obj, const float* __restrict__ b_ctx,
    const float* __restrict__ b_co, float* __restrict__ out) {
    __shared__ int    ss[4][32];
    __shared__ float4 spA[4][32];
    __shared__ float2 spB[4][32];
    int w = threadIdx.x >> 5;
    int gwarp = (blockIdx.x * blockDim.x + threadIdx.x) >> 5;
    int lane = threadIdx.x & 31;
    if (gwarp >= NN) return;
    int n = gwarp;
    int beg = g_rowptr[n], end = g_rowptr[n + 1];

    float4 dA = *(const float4*)(g_aldP + n * 8);
    float2 dB = *(const float2*)(g_aldP + n * 8 + 4);
    float ald[6] = {dA.x, dA.y, dA.z, dA.w, dB.x, dB.y};

    int sub = lane & 15;
    int hh = (lane >> 3) & 1;
    float s[6] = {0, 0, 0, 0, 0, 0};
    float acc0 = 0.f, acc1 = 0.f, acc2 = 0.f;

    for (int base = beg; base < end; base += 32) {
        int idx = base + lane;
        int sl = 0;
        float p[6] = {0, 0, 0, 0, 0, 0};
        if (idx < end) {
            sl = g_srt[idx];
            float4 sA = *(const float4*)(g_alsP + sl * 8);
            float2 sB = *(const float2*)(g_alsP + sl * 8 + 4);
            float als[6] = {sA.x, sA.y, sA.z, sA.w, sB.x, sB.y};
#pragma unroll
            for (int k = 0; k < 6; k++) {
                p[k] = __expf(lrelu(als[k] + ald[k]));
                s[k] += p[k];
            }
        }
        __syncwarp();
        ss[w][lane] = sl;
        spA[w][lane] = make_float4(p[0], p[1], p[2], p[3]);
        spB[w][lane] = make_float2(p[4], p[5]);
        __syncwarp();
        int cnt = min(32, end - base);
        int j = 0;
#pragma unroll 1
        for (; j + 2 <= cnt; j += 2) {
            int sb0 = ss[w][j], sb1 = ss[w][j + 1];
            float4 qA0 = spA[w][j], qA1 = spA[w][j + 1];
            float2 qB0 = spB[w][j], qB1 = spB[w][j + 1];
            const float* g0 = g_gall + (size_t)sb0 * 48;
            const float* g1 = g_gall + (size_t)sb1 * 48;
            float x00 = g0[sub], x01 = g0[16 + sub], x02 = g0[32 + sub];
            float x10 = g1[sub], x11 = g1[16 + sub], x12 = g1[32 + sub];
            acc0 += (hh ? qA0.y : qA0.x) * x00 + (hh ? qA1.y : qA1.x) * x10;
            acc1 += (hh ? qA0.w : qA0.z) * x01 + (hh ? qA1.w : qA1.z) * x11;
            acc2 += (hh ? qB0.y : qB0.x) * x02 + (hh ? qB1.y : qB1.x) * x12;
        }
        if (j < cnt) {
            int sb = ss[w][j];
            float4 qA = spA[w][j];
            float2 qB = spB[w][j];
            const float* gr = g_gall + (size_t)sb * 48;
            acc0 += (hh ? qA.y : qA.x) * gr[sub];
            acc1 += (hh ? qA.w : qA.z) * gr[16 + sub];
            acc2 += (hh ? qB.y : qB.x) * gr[32 + sub];
        }
    }

    for (int o = 16; o; o >>= 1) {
#pragma unroll
        for (int k = 0; k < 6; k++) s[k] += __shfl_xor_sync(~0u, s[k], o);
    }
    acc0 *= 1.f / (s[hh] + 1e-16f);
    acc1 *= 1.f / (s[2 + hh] + 1e-16f);
    acc2 *= 1.f / (s[4 + hh] + 1e-16f);

    float v0 = 0.5f * (acc0 + __shfl_xor_sync(~0u, acc0, 8)) + b_obj[lane & 7];
    float v1 = 0.5f * (acc1 + __shfl_xor_sync(~0u, acc1, 8)) + b_ctx[lane & 7];
    float v2 = 0.5f * (acc2 + __shfl_xor_sync(~0u, acc2, 8)) + b_co[lane & 7];
    float mv0 = v0, mv1 = v1, mv2 = v2;
    for (int o = 4; o; o >>= 1) {
        mv0 = fmaxf(mv0, __shfl_xor_sync(~0u, mv0, o, 8));
        mv1 = fmaxf(mv1, __shfl_xor_sync(~0u, mv1, o, 8));
        mv2 = fmaxf(mv2, __shfl_xor_sync(~0u, mv2, o, 8));
    }
    float se0 = __expf(v0 - mv0), se1 = __expf(v1 - mv1), se2 = __expf(v2 - mv2);
    for (int o = 4; o; o >>= 1) {
        se0 += __shfl_xor_sync(~0u, se0, o, 8);
        se1 += __shfl_xor_sync(~0u, se1, o, 8);
        se2 += __shfl_xor_sync(~0u, se2, o, 8);
    }
    if (lane < 8) {
        stcs1(out + O0 + (size_t)n * 8 + lane, v0 - mv0 - __logf(se0));
        stcs1(out + O1 + (size_t)n * 8 + lane, v1 - mv1 - __logf(se1));
        stcs1(out + O2 + (size_t)n * 8 + lane, v2 - mv2 - __logf(se2));
    }
}

// ------------------- launch -------------------
extern "C" void kernel_launch(void* const* d_in, const int* in_sizes, int n_in,
                              void* d_out, int out_size) {
    const float* x      = (const float*)d_in[0];
    const int*   ei     = (const int*)d_in[1];
    const float* W_feat = (const float*)d_in[2];
    const float* a_s_f  = (const float*)d_in[3];
    const float* a_d_f  = (const float*)d_in[4];
    const float* b_feat = (const float*)d_in[5];
    const float* W_mlp  = (const float*)d_in[6];
    const float* b_mlp  = (const float*)d_in[7];
    const float* W_obj  = (const float*)d_in[8];
    const float* a_s_o  = (const float*)d_in[9];
    const float* a_d_o  = (const float*)d_in[10];
    const float* b_obj  = (const float*)d_in[11];
    const float* W_ctx  = (const float*)d_in[12];
    const float* a_s_c  = (const float*)d_in[13];
    const float* a_d_c  = (const float*)d_in[14];
    const float* b_ctx  = (const float*)d_in[15];
    const float* W_co   = (const float*)d_in[16];
    const float* a_s_x  = (const float*)d_in[17];
    const float* a_d_x  = (const float*)d_in[18];
    const float* b_co   = (const float*)d_in[19];
    float* out = (float*)d_out;

    const int GEMM1_SMEM = 128 * 128 * 4 + 2 * 8 * 256 * 4;   // 81920 B
    cudaFuncSetAttribute(k_gemm1, cudaFuncAttributeMaxDynamicSharedMemorySize, GEMM1_SMEM);
    cudaFuncSetAttribute(k_gemm2, cudaFuncAttributeMaxDynamicSharedMemorySize, G2_SMEM);

    // order: conv1 is the 4th launch (ncu capture slot)
    k_gemm1<<<NB1, 512, GEMM1_SMEM>>>(x, W_feat, a_s_f, a_d_f, ei);   // fused hist
    k_scan<<<1, 1024>>>();
    k_scatter<<<(EE / 2 + NN + 255) / 256, 256>>>(ei);
    k_conv1<<<(NN + 3) / 4, 128>>>(b_feat, W_mlp, b_mlp, out);

    k_gemm2<<<NB2, 256, G2_SMEM>>>(W_obj, W_ctx, W_co,
                                   a_s_o, a_d_o, a_s_c, a_d_c, a_s_x, a_d_x);
    k_conv2m<<<(NN + 3) / 4, 128>>>(b_obj, b_ctx, b_co, out);
}

// round 17
// speedup vs baseline: 1.4278x; 1.0812x over previous
#include <cuda_runtime.h>
#include <cuda_fp16.h>
#include <cstdint>

#define NN 50000
#define EE 800000
#define ET (EE + NN)
#define NB1 391                       // gemm1 blocks: ceil(50000/128)
#define NB2 391                       // gemm2 blocks: ceil(50000/128)

// output layout: xo_logis [N,8] | xc_logis [N,8] | xco_logis [N,8] | elu(xo) [N,256] | elu(xc) [N,256]
#define O0 0
#define O1 (NN*8)
#define O2 (2*NN*8)
#define O3 (3*NN*8)
#define O4 (3*NN*8 + NN*256)

typedef unsigned long long ull;

__device__ __forceinline__ ull pk2(float lo, float hi) {
    ull r; asm("mov.b64 %0, {%1, %2};" : "=l"(r) : "f"(lo), "f"(hi)); return r;
}
__device__ __forceinline__ void upk2(ull v, float& lo, float& hi) {
    asm("mov.b64 {%0, %1}, %2;" : "=f"(lo), "=f"(hi) : "l"(v));
}
#define FMA2(d, a, b) asm("fma.rn.f32x2 %0, %1, %2, %0;" : "+l"(d) : "l"(a), "l"(b))

__device__ __forceinline__ void stcs4(float* p, float4 v) {
    asm volatile("st.global.cs.v4.f32 [%0], {%1,%2,%3,%4};" :: "l"(p),
                 "f"(v.x), "f"(v.y), "f"(v.z), "f"(v.w) : "memory");
}
__device__ __forceinline__ void stcs1(float* p, float v) {
    asm volatile("st.global.cs.f32 [%0], %1;" :: "l"(p), "f"(v) : "memory");
}

__device__ __forceinline__ uint pack_h2(float a, float b) {
    __half2 h = __floats2half2_rn(a, b);
    return *(uint*)&h;
}
__device__ __forceinline__ float2 unpack_h2(uint u) {
    return __half22float2(*(__half2*)&u);
}

// ------------------- static scratch (zero-initialized at module load) -------------------
__device__ int   g_deg[NN];          // ALWAYS zero at kernel_launch entry (scan re-zeroes)
__device__ int   g_rowptr[NN + 1];
__device__ int   g_wptr[NN];
__device__ int   g_srt[ET];

__device__ __align__(16) __half g_hfeat[(size_t)NN * 256];   // fp16 node features (x @ W_feat)
__device__ __align__(16) __half g_h1[(size_t)NN * 256];      // fp16 post-ELU hidden
__device__ __align__(16) float2 g_att[NN];

__device__ __align__(16) float g_als[NN * 4], g_ald[NN * 4];
__device__ __align__(16) float g_gall[(size_t)NN * 48];
__device__ __align__(16) float g_alsP[NN * 8], g_aldP[NN * 8];

__device__ __forceinline__ float lrelu(float v) { return v > 0.f ? v : 0.2f * v; }
// fast ELU: MUFU-based exp instead of the ~20-instr expm1f software sequence
__device__ __forceinline__ float eluf(float v)  { return v > 0.f ? v : __expf(v) - 1.f; }

// ------------------- CSR hist + scan + scatter (side stream) -------------------
__global__ void k_hist(const int* __restrict__ ei) {
    int i = blockIdx.x * blockDim.x + threadIdx.x;
    if (i >= EE / 2) return;
    int2 d = ((const int2*)(ei + EE))[i];
    atomicAdd(&g_deg[d.x], 1);
    atomicAdd(&g_deg[d.y], 1);
}

__global__ void k_scan() {
    __shared__ int sums[1024];
    int tid = threadIdx.x;
    const int chunk = (NN + 1023) / 1024;
    int start = tid * chunk;
    int s = 0;
    for (int i = 0; i < chunk; i++) {
        int idx = start + i;
        if (idx < NN) s += g_deg[idx] + 1;   // +1 = self loop
    }
    sums[tid] = s;
    __syncthreads();
    for (int off = 1; off < 1024; off <<= 1) {
        int v = 0;
        if (tid >= off) v = sums[tid - off];
        __syncthreads();
        if (tid >= off) sums[tid] += v;
        __syncthreads();
    }
    int prefix = (tid == 0) ? 0 : sums[tid - 1];
    for (int i = 0; i < chunk; i++) {
        int idx = start + i;
        if (idx < NN) {
            g_rowptr[idx] = prefix;
            g_wptr[idx] = prefix;
            prefix += g_deg[idx] + 1;
            g_deg[idx] = 0;                  // restore invariant for next call
        }
    }
    if (tid == 0) g_rowptr[NN] = sums[1023];
}

__global__ void k_scatter(const int* __restrict__ ei) {
    int i = blockIdx.x * blockDim.x + threadIdx.x;
    if (i < EE / 2) {
        int2 s2 = ((const int2*)ei)[i];
        int2 d2 = ((const int2*)(ei + EE))[i];
        int p0 = atomicAdd(&g_wptr[d2.x], 1);
        g_srt[p0] = s2.x;
        int p1 = atomicAdd(&g_wptr[d2.y], 1);
        g_srt[p1] = s2.y;
    } else if (i < EE / 2 + NN) {
        int n = i - EE / 2;
        int pos = atomicAdd(&g_wptr[n], 1);
        g_srt[pos] = n;                      // self loop
    }
}

// ------------------- GEMM1: 128x256 tile, 512 thr, thread = 8 rows x (4+4 cols) -------------------
__global__ __launch_bounds__(512) void k_gemm1(
    const float* __restrict__ x, const float* __restrict__ Wf,
    const float* __restrict__ a_s, const float* __restrict__ a_d) {
    extern __shared__ float smem[];
    float (*xs)[128] = (float (*)[128])smem;                        // 128 x 128 = 64 KB
    float (*Bs)[8][256] = (float (*)[8][256])(smem + 128 * 128);    // [2][8][256] = 16 KB
    int tid = threadIdx.x;
    int n0 = blockIdx.x * 128;
    int ty = tid >> 5, tx = tid & 31;       // ty 0..15 -> 8-row group

    // fill xs: 4096 float4, 8 per thread
#pragma unroll
    for (int i = 0; i < 8; i++) {
        int idx4 = tid + i * 512;
        int row = idx4 >> 5, kq = idx4 & 31;
        float4 v = make_float4(0, 0, 0, 0);
        if (n0 + row < NN) v = *(const float4*)(x + (size_t)(n0 + row) * 128 + kq * 4);
        *(float4*)&xs[row][kq * 4] = v;
    }

    // prefetch kt=0 W slab
    int pkk = tid >> 6, pcc = (tid & 63) * 4;
    float4 pre = *(const float4*)(Wf + (size_t)pkk * 256 + pcc);
    *(float4*)&Bs[0][pkk][pcc] = pre;

    float4 asA = *(const float4*)(a_s + tx * 4);
    float4 asB = *(const float4*)(a_s + 128 + tx * 4);
    float4 adA = *(const float4*)(a_d + tx * 4);
    float4 adB = *(const float4*)(a_d + 128 + tx * 4);

    ull accp[8][4];
#pragma unroll
    for (int i = 0; i < 8; i++)
#pragma unroll
        for (int j = 0; j < 4; j++) accp[i][j] = 0ull;

    __syncthreads();

    for (int kt = 0; kt < 16; kt++) {
        if (kt < 15)
            pre = *(const float4*)(Wf + (size_t)((kt + 1) * 8 + pkk) * 256 + pcc);
        const float (*B)[256] = Bs[kt & 1];
#pragma unroll
        for (int half = 0; half < 2; half++) {
            {
                ull b[4][2];
#pragma unroll
                for (int kk = 0; kk < 4; kk++) {
                    float4 t = *(const float4*)&B[half * 4 + kk][tx * 4];
                    b[kk][0] = pk2(t.x, t.y); b[kk][1] = pk2(t.z, t.w);
                }
#pragma unroll
                for (int i = 0; i < 8; i++) {
                    float4 af = *(const float4*)&xs[ty * 8 + i][kt * 8 + half * 4];
                    ull a0 = pk2(af.x, af.x), a1 = pk2(af.y, af.y);
                    ull a2 = pk2(af.z, af.z), a3 = pk2(af.w, af.w);
                    FMA2(accp[i][0], a0, b[0][0]); FMA2(accp[i][1], a0, b[0][1]);
                    FMA2(accp[i][0], a1, b[1][0]); FMA2(accp[i][1], a1, b[1][1]);
                    FMA2(accp[i][0], a2, b[2][0]); FMA2(accp[i][1], a2, b[2][1]);
                    FMA2(accp[i][0], a3, b[3][0]); FMA2(accp[i][1], a3, b[3][1]);
                }
            }
            {
                ull b[4][2];
#pragma unroll
                for (int kk = 0; kk < 4; kk++) {
                    float4 t = *(const float4*)&B[half * 4 + kk][128 + tx * 4];
                    b[kk][0] = pk2(t.x, t.y); b[kk][1] = pk2(t.z, t.w);
                }
#pragma unroll
                for (int i = 0; i < 8; i++) {
                    float4 af = *(const float4*)&xs[ty * 8 + i][kt * 8 + half * 4];
                    ull a0 = pk2(af.x, af.x), a1 = pk2(af.y, af.y);
                    ull a2 = pk2(af.z, af.z), a3 = pk2(af.w, af.w);
                    FMA2(accp[i][2], a0, b[0][0]); FMA2(accp[i][3], a0, b[0][1]);
                    FMA2(accp[i][2], a1, b[1][0]); FMA2(accp[i][3], a1, b[1][1]);
                    FMA2(accp[i][2], a2, b[2][0]); FMA2(accp[i][3], a2, b[2][1]);
                    FMA2(accp[i][2], a3, b[3][0]); FMA2(accp[i][3], a3, b[3][1]);
                }
            }
        }
        if (kt < 15) {
            *(float4*)&Bs[(kt + 1) & 1][pkk][pcc] = pre;
            __syncthreads();
        }
    }

    // epilogue: store hfeat (fp16) + fused attention-logit dots (fp32)
#pragma unroll
    for (int i = 0; i < 8; i++) {
        int row = n0 + ty * 8 + i;
        bool ok = row < NN;
        float4 vA, vB;
        upk2(accp[i][0], vA.x, vA.y); upk2(accp[i][1], vA.z, vA.w);
        upk2(accp[i][2], vB.x, vB.y); upk2(accp[i][3], vB.z, vB.w);
        if (ok) {
            uint2 uA, uB;
            uA.x = pack_h2(vA.x, vA.y); uA.y = pack_h2(vA.z, vA.w);
            uB.x = pack_h2(vB.x, vB.y); uB.y = pack_h2(vB.z, vB.w);
            *(uint2*)(g_hfeat + (size_t)row * 256 + tx * 4)       = uA;
            *(uint2*)(g_hfeat + (size_t)row * 256 + 128 + tx * 4) = uB;
        }
        float psA = vA.x * asA.x + vA.y * asA.y + vA.z * asA.z + vA.w * asA.w;
        float psB = vB.x * asB.x + vB.y * asB.y + vB.z * asB.z + vB.w * asB.w;
        float pdA = vA.x * adA.x + vA.y * adA.y + vA.z * adA.z + vA.w * adA.w;
        float pdB = vB.x * adB.x + vB.y * adB.y + vB.z * adB.z + vB.w * adB.w;
        for (int o = 1; o < 16; o <<= 1) {
            psA += __shfl_xor_sync(~0u, psA, o);
            psB += __shfl_xor_sync(~0u, psB, o);
            pdA += __shfl_xor_sync(~0u, pdA, o);
            pdB += __shfl_xor_sync(~0u, pdB, o);
        }
        if ((tx & 15) == 0 && ok) {
            int hA = tx >> 4;
            g_als[row * 4 + hA]     = psA;
            g_als[row * 4 + 2 + hA] = psB;
            g_ald[row * 4 + hA]     = pdA;
            g_ald[row * 4 + 2 + hA] = pdB;
        }
    }
}

// ------------------- big conv: warp per dst node, single pass, fp16 gather -------------------
__global__ __launch_bounds__(128) void k_conv1(
    const float* __restrict__ b_feat, const float* __restrict__ W_mlp,
    const float* __restrict__ b_mlp, float* __restrict__ out) {
    __shared__ int    ss[4][32];
    __shared__ float4 sp[4][32];
    int w = threadIdx.x >> 5;
    int gwarp = (blockIdx.x * blockDim.x + threadIdx.x) >> 5;
    int lane = threadIdx.x & 31;
    if (gwarp >= NN) return;
    int n = gwarp;
    int beg = g_rowptr[n], end = g_rowptr[n + 1];

    const float4* als4 = (const float4*)g_als;
    float4 ad = ((const float4*)g_ald)[n];
    bool lo16 = lane < 16;

    float s0 = 0.f, s1 = 0.f, s2 = 0.f, s3 = 0.f;
    ull acc0 = 0, acc1 = 0, acc2 = 0, acc3 = 0;

    for (int base = beg; base < end; base += 32) {
        int idx = base + lane;
        int sl = 0;
        float4 pv = make_float4(0, 0, 0, 0);
        if (idx < end) {
            sl = g_srt[idx];
            float4 as = als4[sl];
            pv.x = __expf(lrelu(as.x + ad.x));
            pv.y = __expf(lrelu(as.y + ad.y));
            pv.z = __expf(lrelu(as.z + ad.z));
            pv.w = __expf(lrelu(as.w + ad.w));
            s0 += pv.x; s1 += pv.y; s2 += pv.z; s3 += pv.w;
        }
        __syncwarp();
        ss[w][lane] = sl;
        sp[w][lane] = pv;
        __syncwarp();
        int cnt = min(32, end - base);
        int j = 0;
#pragma unroll 1
        for (; j + 2 <= cnt; j += 2) {
            int sb0 = ss[w][j], sb1 = ss[w][j + 1];
            float4 pj0 = sp[w][j], pj1 = sp[w][j + 1];
            const uint2* hr0 = (const uint2*)(g_hfeat + (size_t)sb0 * 256);
            const uint2* hr1 = (const uint2*)(g_hfeat + (size_t)sb1 * 256);
            uint2 hA0 = hr0[lane], hB0 = hr0[lane + 32];
            uint2 hA1 = hr1[lane], hB1 = hr1[lane + 32];
            float aA0 = lo16 ? pj0.x : pj0.y, aB0 = lo16 ? pj0.z : pj0.w;
            float aA1 = lo16 ? pj1.x : pj1.y, aB1 = lo16 ? pj1.z : pj1.w;
            ull aA0p = pk2(aA0, aA0), aB0p = pk2(aB0, aB0);
            ull aA1p = pk2(aA1, aA1), aB1p = pk2(aB1, aB1);
            float2 fA0a = unpack_h2(hA0.x), fA0b = unpack_h2(hA0.y);
            float2 fB0a = unpack_h2(hB0.x), fB0b = unpack_h2(hB0.y);
            float2 fA1a = unpack_h2(hA1.x), fA1b = unpack_h2(hA1.y);
            float2 fB1a = unpack_h2(hB1.x), fB1b = unpack_h2(hB1.y);
            FMA2(acc0, aA0p, pk2(fA0a.x, fA0a.y));
            FMA2(acc1, aA0p, pk2(fA0b.x, fA0b.y));
            FMA2(acc2, aB0p, pk2(fB0a.x, fB0a.y));
            FMA2(acc3, aB0p, pk2(fB0b.x, fB0b.y));
            FMA2(acc0, aA1p, pk2(fA1a.x, fA1a.y));
            FMA2(acc1, aA1p, pk2(fA1b.x, fA1b.y));
            FMA2(acc2, aB1p, pk2(fB1a.x, fB1a.y));
            FMA2(acc3, aB1p, pk2(fB1b.x, fB1b.y));
        }
        if (j < cnt) {
            int sb = ss[w][j];
            float4 pj = sp[w][j];
            const uint2* hr = (const uint2*)(g_hfeat + (size_t)sb * 256);
            uint2 hA = hr[lane], hB = hr[lane + 32];
            float aA = lo16 ? pj.x : pj.y, aB = lo16 ? pj.z : pj.w;
            ull aAp = pk2(aA, aA), aBp = pk2(aB, aB);
            float2 fAa = unpack_h2(hA.x), fAb = unpack_h2(hA.y);
            float2 fBa = unpack_h2(hB.x), fBb = unpack_h2(hB.y);
            FMA2(acc0, aAp, pk2(fAa.x, fAa.y));
            FMA2(acc1, aAp, pk2(fAb.x, fAb.y));
            FMA2(acc2, aBp, pk2(fBa.x, fBa.y));
            FMA2(acc3, aBp, pk2(fBb.x, fBb.y));
        }
    }

    for (int o = 16; o; o >>= 1) {
        s0 += __shfl_xor_sync(~0u, s0, o);
        s1 += __shfl_xor_sync(~0u, s1, o);
        s2 += __shfl_xor_sync(~0u, s2, o);
        s3 += __shfl_xor_sync(~0u, s3, o);
    }
    float i0 = 1.f / (s0 + 1e-16f), i1 = 1.f / (s1 + 1e-16f);
    float i2 = 1.f / (s2 + 1e-16f), i3 = 1.f / (s3 + 1e-16f);
    float invA = lo16 ? i0 : i1;
    float invB = lo16 ? i2 : i3;

    float a0, a1, a2, a3, b0, b1, b2, b3;
    upk2(acc0, a0, a1); upk2(acc1, a2, a3);
    upk2(acc2, b0, b1); upk2(acc3, b2, b3);
    float4 bfA = *(const float4*)(b_feat + 4 * lane);
    float4 bfB = *(const float4*)(b_feat + 128 + 4 * lane);
    float heA0 = eluf(a0 * invA + bfA.x), heA1 = eluf(a1 * invA + bfA.y);
    float heA2 = eluf(a2 * invA + bfA.z), heA3 = eluf(a3 * invA + bfA.w);
    float heB0 = eluf(b0 * invB + bfB.x), heB1 = eluf(b1 * invB + bfB.y);
    float heB2 = eluf(b2 * invB + bfB.z), heB3 = eluf(b3 * invB + bfB.w);
    {
        uint2 uA, uB;
        uA.x = pack_h2(heA0, heA1); uA.y = pack_h2(heA2, heA3);
        uB.x = pack_h2(heB0, heB1); uB.y = pack_h2(heB2, heB3);
        *(uint2*)(g_h1 + (size_t)n * 256 + 4 * lane)       = uA;
        *(uint2*)(g_h1 + (size_t)n * 256 + 128 + 4 * lane) = uB;
    }

    float4 wA0 = *(const float4*)(W_mlp + 8 * lane);
    float4 wA1 = *(const float4*)(W_mlp + 8 * lane + 4);
    float4 wB0 = *(const float4*)(W_mlp + 256 + 8 * lane);
    float4 wB1 = *(const float4*)(W_mlp + 256 + 8 * lane + 4);
    float l0 = heA0 * wA0.x + heA1 * wA0.z + heA2 * wA1.x + heA3 * wA1.z
             + heB0 * wB0.x + heB1 * wB0.z + heB2 * wB1.x + heB3 * wB1.z;
    float l1 = heA0 * wA0.y + heA1 * wA0.w + heA2 * wA1.y + heA3 * wA1.w
             + heB0 * wB0.y + heB1 * wB0.w + heB2 * wB1.y + heB3 * wB1.w;
    for (int o = 16; o; o >>= 1) {
        l0 += __shfl_xor_sync(~0u, l0, o);
        l1 += __shfl_xor_sync(~0u, l1, o);
    }
    l0 += b_mlp[0];
    l1 += b_mlp[1];
    float mm = fmaxf(l0, l1);
    float e0 = __expf(l0 - mm), e1 = __expf(l1 - mm);
    float inv2 = 1.f / (e0 + e1);
    float att0 = e0 * inv2, att1 = e1 * inv2;
    if (lane == 0) g_att[n] = make_float2(att0, att1);

    stcs4(out + O3 + (size_t)n * 256 + 4 * lane,
          make_float4(eluf(att0 * heA0), eluf(att0 * heA1), eluf(att0 * heA2), eluf(att0 * heA3)));
    stcs4(out + O3 + (size_t)n * 256 + 128 + 4 * lane,
          make_float4(eluf(att0 * heB0), eluf(att0 * heB1), eluf(att0 * heB2), eluf(att0 * heB3)));
    stcs4(out + O4 + (size_t)n * 256 + 4 * lane,
          make_float4(eluf(att1 * heA0), eluf(att1 * heA1), eluf(att1 * heA2), eluf(att1 * heA3)));
    stcs4(out + O4 + (size_t)n * 256 + 128 + 4 * lane,
          make_float4(eluf(att1 * heB0), eluf(att1 * heB1), eluf(att1 * heB2), eluf(att1 * heB3)));
}

// ------------------- GEMM2 (register-tiled): Y[N,48] = h1 @ [Wo|Wc|Wx], att-scaled, + al dots -------------------
#define G2_ASTRIDE 68
#define G2_WSTRIDE 66
#define G2_YSTRIDE 50
#define G2_SMEM (128 * G2_ASTRIDE * 4 + 48 * G2_WSTRIDE * 4)

__global__ __launch_bounds__(256) void k_gemm2(
    const float* __restrict__ Wo, const float* __restrict__ Wc, const float* __restrict__ Wx,
    const float* __restrict__ aso, const float* __restrict__ ado,
    const float* __restrict__ asc, const float* __restrict__ adc,
    const float* __restrict__ asx, const float* __restrict__ adx) {
    extern __shared__ float smem[];
    float* As = smem;                          // [128][68]
    float* Wt = smem + 128 * G2_ASTRIDE;       // [48][66], k-contiguous
    float* ysm = smem;                         // [128][50], reuses A after compute

    int tid = threadIdx.x;
    int n0 = blockIdx.x * 128;
    int ty = tid >> 4, tx = tid & 15;

    ull acc[8][3];
#pragma unroll
    for (int i = 0; i < 8; i++)
#pragma unroll
        for (int v = 0; v < 3; v++) acc[i][v] = 0ull;

    for (int ch = 0; ch < 4; ch++) {           // K chunks of 64
        __syncthreads();
#pragma unroll
        for (int i = 0; i < 8; i++) {
            int idx4 = tid + i * 256;
            int row = idx4 >> 4, q = idx4 & 15;
            float4 v = make_float4(0, 0, 0, 0);
            if (n0 + row < NN) {
                uint2 u = *(const uint2*)(g_h1 + (size_t)(n0 + row) * 256 + ch * 64 + q * 4);
                float2 f01 = unpack_h2(u.x), f23 = unpack_h2(u.y);
                v = make_float4(f01.x, f01.y, f23.x, f23.y);
            }
            *(float4*)&As[row * G2_ASTRIDE + q * 4] = v;
        }
#pragma unroll
        for (int i = 0; i < 12; i++) {
            int idx = tid + i * 256;
            int ca = idx >> 6, kk = idx & 63;
            int v = ca >> 4, c = ca & 15;
            const float* W = (v == 0) ? Wo : (v == 1) ? Wc : Wx;
            Wt[ca * G2_WSTRIDE + kk] = W[(size_t)(ch * 64 + kk) * 16 + c];
        }
        __syncthreads();
#pragma unroll 8
        for (int kp = 0; kp < 32; kp++) {
            ull w0 = *(const ull*)&Wt[tx * G2_WSTRIDE + kp * 2];
            ull w1 = *(const ull*)&Wt[(16 + tx) * G2_WSTRIDE + kp * 2];
            ull w2 = *(const ull*)&Wt[(32 + tx) * G2_WSTRIDE + kp * 2];
#pragma unroll
            for (int i = 0; i < 8; i++) {
                ull a = *(const ull*)&As[(ty * 8 + i) * G2_ASTRIDE + kp * 2];
                FMA2(acc[i][0], a, w0);
                FMA2(acc[i][1], a, w1);
                FMA2(acc[i][2], a, w2);
            }
        }
    }

    __syncthreads();   // done reading As; ysm may overwrite

#pragma unroll
    for (int i = 0; i < 8; i++) {
        int lrow = ty * 8 + i;
        int row = n0 + lrow;
        float lo, hi;
        upk2(acc[i][0], lo, hi); float y0 = lo + hi;
        upk2(acc[i][1], lo, hi); float y1 = lo + hi;
        upk2(acc[i][2], lo, hi); float y2 = lo + hi;
        if (row < NN) {
            float2 att = g_att[row];
            y0 *= att.x;
            y1 *= att.y;
            float* gr = g_gall + (size_t)row * 48;
            gr[tx] = y0; gr[16 + tx] = y1; gr[32 + tx] = y2;
        }
        ysm[lrow * G2_YSTRIDE + tx]      = y0;
        ysm[lrow * G2_YSTRIDE + 16 + tx] = y1;
        ysm[lrow * G2_YSTRIDE + 32 + tx] = y2;
    }
    __syncthreads();

#pragma unroll
    for (int j = 0; j < 6; j++) {
        int d = tid * 6 + j;
        int nl = d / 12, r = d % 12;
        int v = r >> 2, h = (r >> 1) & 1, sd = r & 1;
        int row = n0 + nl;
        if (row >= NN) continue;
        const float* a = sd ? ((v == 0) ? ado : (v == 1) ? adc : adx)
                            : ((v == 0) ? aso : (v == 1) ? asc : asx);
        const float* yy = ysm + nl * G2_YSTRIDE + v * 16 + h * 8;
        float s = 0.f;
#pragma unroll
        for (int o = 0; o < 8; o++) s += yy[o] * a[h * 8 + o];
        float* dstp = sd ? g_aldP : g_alsP;
        dstp[row * 8 + v * 2 + h] = s;
    }
}

// ------------------- merged small convs: warp per dst node, single pass, unrolled -------------------
__global__ __launch_bounds__(128) void k_conv2m(
    const float* __restrict__ b_obj, const float* __restrict__ b_ctx,
    const float* __restrict__ b_co, float* __restrict__ out) {
    __shared__ int    ss[4][32];
    __shared__ float4 spA[4][32];
    __shared__ float2 spB[4][32];
    int w = threadIdx.x >> 5;
    int gwarp = (blockIdx.x * blockDim.x + threadIdx.x) >> 5;
    int lane = threadIdx.x & 31;
    if (gwarp >= NN) return;
    int n = gwarp;
    int beg = g_rowptr[n], end = g_rowptr[n + 1];

    float4 dA = *(const float4*)(g_aldP + n * 8);
    float2 dB = *(const float2*)(g_aldP + n * 8 + 4);
    float ald[6] = {dA.x, dA.y, dA.z, dA.w, dB.x, dB.y};

    int sub = lane & 15;
    int hh = (lane >> 3) & 1;
    float s[6] = {0, 0, 0, 0, 0, 0};
    float acc0 = 0.f, acc1 = 0.f, acc2 = 0.f;

    for (int base = beg; base < end; base += 32) {
        int idx = base + lane;
        int sl = 0;
        float p[6] = {0, 0, 0, 0, 0, 0};
        if (idx < end) {
            sl = g_srt[idx];
            float4 sA = *(const float4*)(g_alsP + sl * 8);
            float2 sB = *(const float2*)(g_alsP + sl * 8 + 4);
            float als[6] = {sA.x, sA.y, sA.z, sA.w, sB.x, sB.y};
#pragma unroll
            for (int k = 0; k < 6; k++) {
                p[k] = __expf(lrelu(als[k] + ald[k]));
                s[k] += p[k];
            }
        }
        __syncwarp();
        ss[w][lane] = sl;
        spA[w][lane] = make_float4(p[0], p[1], p[2], p[3]);
        spB[w][lane] = make_float2(p[4], p[5]);
        __syncwarp();
        int cnt = min(32, end - base);
        int j = 0;
#pragma unroll 1
        for (; j + 2 <= cnt; j += 2) {
            int sb0 = ss[w][j], sb1 = ss[w][j + 1];
            float4 qA0 = spA[w][j], qA1 = spA[w][j + 1];
            float2 qB0 = spB[w][j], qB1 = spB[w][j + 1];
            const float* g0 = g_gall + (size_t)sb0 * 48;
            const float* g1 = g_gall + (size_t)sb1 * 48;
            float x00 = g0[sub], x01 = g0[16 + sub], x02 = g0[32 + sub];
            float x10 = g1[sub], x11 = g1[16 + sub], x12 = g1[32 + sub];
            acc0 += (hh ? qA0.y : qA0.x) * x00 + (hh ? qA1.y : qA1.x) * x10;
            acc1 += (hh ? qA0.w : qA0.z) * x01 + (hh ? qA1.w : qA1.z) * x11;
            acc2 += (hh ? qB0.y : qB0.x) * x02 + (hh ? qB1.y : qB1.x) * x12;
        }
        if (j < cnt) {
            int sb = ss[w][j];
            float4 qA = spA[w][j];
            float2 qB = spB[w][j];
            const float* gr = g_gall + (size_t)sb * 48;
            acc0 += (hh ? qA.y : qA.x) * gr[sub];
            acc1 += (hh ? qA.w : qA.z) * gr[16 + sub];
            acc2 += (hh ? qB.y : qB.x) * gr[32 + sub];
        }
    }

    for (int o = 16; o; o >>= 1) {
#pragma unroll
        for (int k = 0; k < 6; k++) s[k] += __shfl_xor_sync(~0u, s[k], o);
    }
    acc0 *= 1.f / (s[hh] + 1e-16f);
    acc1 *= 1.f / (s[2 + hh] + 1e-16f);
    acc2 *= 1.f / (s[4 + hh] + 1e-16f);

    float v0 = 0.5f * (acc0 + __shfl_xor_sync(~0u, acc0, 8)) + b_obj[lane & 7];
    float v1 = 0.5f * (acc1 + __shfl_xor_sync(~0u, acc1, 8)) + b_ctx[lane & 7];
    float v2 = 0.5f * (acc2 + __shfl_xor_sync(~0u, acc2, 8)) + b_co[lane & 7];
    float mv0 = v0, mv1 = v1, mv2 = v2;
    for (int o = 4; o; o >>= 1) {
        mv0 = fmaxf(mv0, __shfl_xor_sync(~0u, mv0, o, 8));
        mv1 = fmaxf(mv1, __shfl_xor_sync(~0u, mv1, o, 8));
        mv2 = fmaxf(mv2, __shfl_xor_sync(~0u, mv2, o, 8));
    }
    float se0 = __expf(v0 - mv0), se1 = __expf(v1 - mv1), se2 = __expf(v2 - mv2);
    for (int o = 4; o; o >>= 1) {
        se0 += __shfl_xor_sync(~0u, se0, o, 8);
        se1 += __shfl_xor_sync(~0u, se1, o, 8);
        se2 += __shfl_xor_sync(~0u, se2, o, 8);
    }
    if (lane < 8) {
        stcs1(out + O0 + (size_t)n * 8 + lane, v0 - mv0 - __logf(se0));
        stcs1(out + O1 + (size_t)n * 8 + lane, v1 - mv1 - __logf(se1));
        stcs1(out + O2 + (size_t)n * 8 + lane, v2 - mv2 - __logf(se2));
    }
}

// ------------------- launch (fork-join: CSR on side stream ∥ gemm1) -------------------
extern "C" void kernel_launch(void* const* d_in, const int* in_sizes, int n_in,
                              void* d_out, int out_size) {
    const float* x      = (const float*)d_in[0];
    const int*   ei     = (const int*)d_in[1];
    const float* W_feat = (const float*)d_in[2];
    const float* a_s_f  = (const float*)d_in[3];
    const float* a_d_f  = (const float*)d_in[4];
    const float* b_feat = (const float*)d_in[5];
    const float* W_mlp  = (const float*)d_in[6];
    const float* b_mlp  = (const float*)d_in[7];
    const float* W_obj  = (const float*)d_in[8];
    const float* a_s_o  = (const float*)d_in[9];
    const float* a_d_o  = (const float*)d_in[10];
    const float* b_obj  = (const float*)d_in[11];
    const float* W_ctx  = (const float*)d_in[12];
    const float* a_s_c  = (const float*)d_in[13];
    const float* a_d_c  = (const float*)d_in[14];
    const float* b_ctx  = (const float*)d_in[15];
    const float* W_co   = (const float*)d_in[16];
    const float* a_s_x  = (const float*)d_in[17];
    const float* a_d_x  = (const float*)d_in[18];
    const float* b_co   = (const float*)d_in[19];
    float* out = (float*)d_out;

    static cudaStream_t s2 = nullptr;
    static cudaEvent_t eFork = nullptr, eJoin = nullptr;
    if (!s2) {
        cudaStreamCreateWithFlags(&s2, cudaStreamNonBlocking);
        cudaEventCreateWithFlags(&eFork, cudaEventDisableTiming);
        cudaEventCreateWithFlags(&eJoin, cudaEventDisableTiming);
        const int GEMM1_SMEM_I = 128 * 128 * 4 + 2 * 8 * 256 * 4;
        cudaFuncSetAttribute(k_gemm1, cudaFuncAttributeMaxDynamicSharedMemorySize, GEMM1_SMEM_I);
        cudaFuncSetAttribute(k_gemm2, cudaFuncAttributeMaxDynamicSharedMemorySize, G2_SMEM);
    }
    const int GEMM1_SMEM = 128 * 128 * 4 + 2 * 8 * 256 * 4;   // 81920 B

    // fork: CSR chain on side stream, concurrent with gemm1 on main stream
    cudaEventRecord(eFork, 0);
    cudaStreamWaitEvent(s2, eFork, 0);
    k_hist<<<(EE / 2 + 255) / 256, 256, 0, s2>>>(ei);
    k_scan<<<1, 1024, 0, s2>>>();
    k_scatter<<<(EE / 2 + NN + 255) / 256, 256, 0, s2>>>(ei);
    cudaEventRecord(eJoin, s2);

    k_gemm1<<<NB1, 512, GEMM1_SMEM>>>(x, W_feat, a_s_f, a_d_f);   // 4th launch: ncu slot

    // join
    cudaStreamWaitEvent(0, eJoin, 0);

    k_conv1<<<(NN + 3) / 4, 128>>>(b_feat, W_mlp, b_mlp, out);
    k_gemm2<<<NB2, 256, G2_SMEM>>>(W_obj, W_ctx, W_co,
                                   a_s_o, a_d_o, a_s_c, a_d_c, a_s_x, a_d_x);
    k_conv2m<<<(NN + 3) / 4, 128>>>(b_obj, b_ctx, b_co, out);
}